// round 3
// baseline (speedup 1.0000x reference)
#include <cuda_runtime.h>

#define N_NODES 8192
#define D_IN    512
#define D_OUT   256
#define ALPHA   0.2f

// Scratch (allocation-free rule: __device__ globals)
__device__ float g_h[N_NODES * D_OUT];   // 8 MB
__device__ float g_mu[N_NODES];
__device__ float g_xi[N_NODES];

// ---------------------------------------------------------------------------
// Kernel A: h = X[8192,512] @ W[512,256]  (fp32, tiled 64x64, 4x4 microtiles)
// ---------------------------------------------------------------------------
__global__ __launch_bounds__(256) void gemm_xw(const float* __restrict__ X,
                                               const float* __restrict__ W) {
    __shared__ float Xst[32][64];   // [k][r] transposed
    __shared__ float Ws[32][64];    // [k][c]
    const int tid = threadIdx.x;
    const int i0 = blockIdx.x * 64;
    const int c0 = blockIdx.y * 64;
    const int r_local = (tid / 16) * 4;
    const int c_local = (tid % 16) * 4;

    float acc[4][4];
#pragma unroll
    for (int a = 0; a < 4; a++)
#pragma unroll
        for (int b = 0; b < 4; b++) acc[a][b] = 0.f;

    for (int k0 = 0; k0 < D_IN; k0 += 32) {
        __syncthreads();
        // Load X tile (64 rows x 32 k), store transposed
#pragma unroll
        for (int t = 0; t < 2; t++) {
            int lin = tid + t * 256;          // 0..511
            int r = lin / 8, kv = lin % 8;
            float4 v = *(const float4*)&X[(i0 + r) * D_IN + k0 + kv * 4];
            Xst[kv * 4 + 0][r] = v.x;
            Xst[kv * 4 + 1][r] = v.y;
            Xst[kv * 4 + 2][r] = v.z;
            Xst[kv * 4 + 3][r] = v.w;
        }
        // Load W tile (32 k x 64 c)
#pragma unroll
        for (int t = 0; t < 2; t++) {
            int lin = tid + t * 256;
            int k = lin / 16, cv = lin % 16;
            *(float4*)&Ws[k][cv * 4] =
                *(const float4*)&W[(k0 + k) * D_OUT + c0 + cv * 4];
        }
        __syncthreads();
#pragma unroll
        for (int k = 0; k < 32; k++) {
            float4 a4 = *(const float4*)&Xst[k][r_local];
            float4 b4 = *(const float4*)&Ws[k][c_local];
            float av[4] = {a4.x, a4.y, a4.z, a4.w};
            float bv[4] = {b4.x, b4.y, b4.z, b4.w};
#pragma unroll
            for (int i = 0; i < 4; i++)
#pragma unroll
                for (int j = 0; j < 4; j++) acc[i][j] += av[i] * bv[j];
        }
    }
#pragma unroll
    for (int i = 0; i < 4; i++) {
        float4 o = make_float4(acc[i][0], acc[i][1], acc[i][2], acc[i][3]);
        *(float4*)&g_h[(i0 + r_local + i) * D_OUT + c0 + c_local] = o;
    }
}

// ---------------------------------------------------------------------------
// Kernel A2: mu = h @ w_mu, xi = h @ w_xi  (warp per row)
// ---------------------------------------------------------------------------
__global__ __launch_bounds__(256) void mu_xi_kernel(const float* __restrict__ wm,
                                                    const float* __restrict__ wx) {
    int warp = (blockIdx.x * blockDim.x + threadIdx.x) >> 5;
    int lane = threadIdx.x & 31;
    if (warp >= N_NODES) return;
    const float* hr = &g_h[warp * D_OUT];
    float mu = 0.f, xi = 0.f;
#pragma unroll
    for (int c = lane; c < D_OUT; c += 32) {
        float v = hr[c];
        mu += v * __ldg(&wm[c]);
        xi += v * __ldg(&wx[c]);
    }
#pragma unroll
    for (int o = 16; o; o >>= 1) {
        mu += __shfl_xor_sync(0xFFFFFFFFu, mu, o);
        xi += __shfl_xor_sync(0xFFFFFFFFu, xi, o);
    }
    if (lane == 0) { g_mu[warp] = mu; g_xi[warp] = xi; }
}

// ---------------------------------------------------------------------------
// Kernel B: fused masked softmax + aggregation, single pass.
// out_i = elu( (sum_j adj_ij * exp(lrelu(mu_i+xi_j)) * h_j) / Z_i )
// Scores are bounded (|e| <= ~4) so no max-subtraction needed; masked terms
// are exactly 0, matching exp(-9e15 - m) == 0 in the reference.
// CTA: 64 rows x 256 cols output block; j-tiles of 32.
// ---------------------------------------------------------------------------
#define BM 64
#define KT 32

__global__ __launch_bounds__(512) void attn_agg(const int* __restrict__ adj,
                                                float* __restrict__ out) {
    __shared__ float Hs[KT][D_OUT];    // 32 KB
    __shared__ float Pt[KT][BM];       // 8 KB, [k][r]
    __shared__ float zbuf[BM * 8];     // 2 KB
    __shared__ float Zs[BM];

    const int tid = threadIdx.x;
    const int i0 = blockIdx.x * BM;

    // P-generation mapping: (pr, pj) -> row pr, j-chunk pj*4
    const int pr = tid >> 3;           // 0..63
    const int pj = tid & 7;            // 0..7
    const float mu_r = g_mu[i0 + pr];

    // Compute mapping: 8 rows x 4 cols microtile
    const int cx = tid & 63;           // col group 0..63 -> cols cx*4..+3
    const int ry = tid >> 6;           // row group 0..7  -> rows ry*8..+7

    float acc[8][4];
#pragma unroll
    for (int a = 0; a < 8; a++)
#pragma unroll
        for (int b = 0; b < 4; b++) acc[a][b] = 0.f;
    float zpart = 0.f;

    for (int j0 = 0; j0 < N_NODES; j0 += KT) {
        __syncthreads();
        // --- P tile: adjacency-masked exp scores ---
        int4 a4 = *(const int4*)&adj[(i0 + pr) * N_NODES + j0 + pj * 4];
        float4 xi4 = *(const float4*)&g_xi[j0 + pj * 4];
        {
            float xs[4] = {xi4.x, xi4.y, xi4.z, xi4.w};
            int am[4] = {a4.x, a4.y, a4.z, a4.w};
#pragma unroll
            for (int kk = 0; kk < 4; kk++) {
                float e = mu_r + xs[kk];
                e = (e >= 0.f) ? e : (ALPHA * e);
                float pv = (am[kk] > 0) ? __expf(e) : 0.f;
                Pt[pj * 4 + kk][pr] = pv;
                zpart += pv;
            }
        }
        // --- H tile: 32 x 256 floats, 4 float4 per thread ---
#pragma unroll
        for (int t = 0; t < 4; t++) {
            int lin = tid + t * 512;        // 0..2047
            int k = lin >> 6, cv = lin & 63;
            *(float4*)&Hs[k][cv * 4] =
                *(const float4*)&g_h[(j0 + k) * D_OUT + cv * 4];
        }
        __syncthreads();
        // --- Register GEMM: acc[8x4] += P[k][8r] * H[k][4c] ---
#pragma unroll 8
        for (int k = 0; k < KT; k++) {
            float4 ha = *(const float4*)&Hs[k][cx * 4];
            float4 pa = *(const float4*)&Pt[k][ry * 8];
            float4 pb = *(const float4*)&Pt[k][ry * 8 + 4];
            float hv[4] = {ha.x, ha.y, ha.z, ha.w};
            float pv[8] = {pa.x, pa.y, pa.z, pa.w, pb.x, pb.y, pb.z, pb.w};
#pragma unroll
            for (int i = 0; i < 8; i++)
#pragma unroll
                for (int j = 0; j < 4; j++) acc[i][j] += pv[i] * hv[j];
        }
    }

    // --- Z reduction ---
    zbuf[pr * 8 + pj] = zpart;
    __syncthreads();
    if (tid < BM) {
        float s = 0.f;
#pragma unroll
        for (int t = 0; t < 8; t++) s += zbuf[tid * 8 + t];
        Zs[tid] = s;
    }
    __syncthreads();

    // --- Epilogue: normalize + ELU ---
#pragma unroll
    for (int i = 0; i < 8; i++) {
        float invz = 1.f / Zs[ry * 8 + i];
        float v0 = acc[i][0] * invz;
        float v1 = acc[i][1] * invz;
        float v2 = acc[i][2] * invz;
        float v3 = acc[i][3] * invz;
        float4 o;
        o.x = (v0 > 0.f) ? v0 : (__expf(v0) - 1.f);
        o.y = (v1 > 0.f) ? v1 : (__expf(v1) - 1.f);
        o.z = (v2 > 0.f) ? v2 : (__expf(v2) - 1.f);
        o.w = (v3 > 0.f) ? v3 : (__expf(v3) - 1.f);
        *(float4*)&out[(i0 + ry * 8 + i) * D_OUT + cx * 4] = o;
    }
}

// ---------------------------------------------------------------------------
extern "C" void kernel_launch(void* const* d_in, const int* in_sizes, int n_in,
                              void* d_out, int out_size) {
    const float* features = (const float*)d_in[0];
    const int*   adj      = (const int*)d_in[1];
    const float* W_phi    = (const float*)d_in[2];
    const float* w_mu     = (const float*)d_in[3];
    const float* w_xi     = (const float*)d_in[4];
    float* out = (float*)d_out;

    (void)in_sizes; (void)n_in; (void)out_size;

    dim3 gA(N_NODES / 64, D_OUT / 64);
    gemm_xw<<<gA, 256>>>(features, W_phi);

    mu_xi_kernel<<<(N_NODES * 32) / 256, 256>>>(w_mu, w_xi);

    attn_agg<<<N_NODES / BM, 512>>>(adj, out);
}

// round 4
// speedup vs baseline: 2.2868x; 2.2868x over previous
#include <cuda_runtime.h>
#include <cstdint>

#define N_NODES 8192
#define D_IN    512
#define D_OUT   256
#define ALPHA   0.2f

// Scratch (allocation-free rule: __device__ globals)
__device__ float g_h [N_NODES * D_OUT];   // fp32 h (for mu/xi)
__device__ float g_ht[N_NODES * D_OUT];   // tf32-rounded h (mma B operand)
__device__ float g_mu[N_NODES];
__device__ float g_xi[N_NODES];

__device__ __forceinline__ float to_tf32(float x) {
    uint32_t u;
    asm("cvt.rna.tf32.f32 %0, %1;" : "=r"(u) : "f"(x));
    return __uint_as_float(u);
}

__device__ __forceinline__ void mma_tf32(float c[4], const uint32_t a[4],
                                         uint32_t b0, uint32_t b1) {
    asm volatile(
        "mma.sync.aligned.m16n8k8.row.col.f32.tf32.tf32.f32 "
        "{%0,%1,%2,%3}, {%4,%5,%6,%7}, {%8,%9}, {%0,%1,%2,%3};"
        : "+f"(c[0]), "+f"(c[1]), "+f"(c[2]), "+f"(c[3])
        : "r"(a[0]), "r"(a[1]), "r"(a[2]), "r"(a[3]), "r"(b0), "r"(b1));
}

// ---------------------------------------------------------------------------
// Kernel A: h = X[8192,512] @ W[512,256]  (fp32, tiled 64x64, 4x4 microtiles)
// Epilogue also writes the tf32-rounded copy g_ht.
// ---------------------------------------------------------------------------
__global__ __launch_bounds__(256) void gemm_xw(const float* __restrict__ X,
                                               const float* __restrict__ W) {
    __shared__ float Xst[32][64];
    __shared__ float Ws[32][64];
    const int tid = threadIdx.x;
    const int i0 = blockIdx.x * 64;
    const int c0 = blockIdx.y * 64;
    const int r_local = (tid / 16) * 4;
    const int c_local = (tid % 16) * 4;

    float acc[4][4];
#pragma unroll
    for (int a = 0; a < 4; a++)
#pragma unroll
        for (int b = 0; b < 4; b++) acc[a][b] = 0.f;

    for (int k0 = 0; k0 < D_IN; k0 += 32) {
        __syncthreads();
#pragma unroll
        for (int t = 0; t < 2; t++) {
            int lin = tid + t * 256;
            int r = lin / 8, kv = lin % 8;
            float4 v = *(const float4*)&X[(i0 + r) * D_IN + k0 + kv * 4];
            Xst[kv * 4 + 0][r] = v.x;
            Xst[kv * 4 + 1][r] = v.y;
            Xst[kv * 4 + 2][r] = v.z;
            Xst[kv * 4 + 3][r] = v.w;
        }
#pragma unroll
        for (int t = 0; t < 2; t++) {
            int lin = tid + t * 256;
            int k = lin / 16, cv = lin % 16;
            *(float4*)&Ws[k][cv * 4] =
                *(const float4*)&W[(k0 + k) * D_OUT + c0 + cv * 4];
        }
        __syncthreads();
#pragma unroll
        for (int k = 0; k < 32; k++) {
            float4 a4 = *(const float4*)&Xst[k][r_local];
            float4 b4 = *(const float4*)&Ws[k][c_local];
            float av[4] = {a4.x, a4.y, a4.z, a4.w};
            float bv[4] = {b4.x, b4.y, b4.z, b4.w};
#pragma unroll
            for (int i = 0; i < 4; i++)
#pragma unroll
                for (int j = 0; j < 4; j++) acc[i][j] += av[i] * bv[j];
        }
    }
#pragma unroll
    for (int i = 0; i < 4; i++) {
        int idx = (i0 + r_local + i) * D_OUT + c0 + c_local;
        float4 o = make_float4(acc[i][0], acc[i][1], acc[i][2], acc[i][3]);
        *(float4*)&g_h[idx] = o;
        float4 ot = make_float4(to_tf32(o.x), to_tf32(o.y),
                                to_tf32(o.z), to_tf32(o.w));
        *(float4*)&g_ht[idx] = ot;
    }
}

// ---------------------------------------------------------------------------
// Kernel A2: mu = h @ w_mu, xi = h @ w_xi  (warp per row)
// ---------------------------------------------------------------------------
__global__ __launch_bounds__(256) void mu_xi_kernel(const float* __restrict__ wm,
                                                    const float* __restrict__ wx) {
    int warp = (blockIdx.x * blockDim.x + threadIdx.x) >> 5;
    int lane = threadIdx.x & 31;
    if (warp >= N_NODES) return;
    const float* hr = &g_h[warp * D_OUT];
    float mu = 0.f, xi = 0.f;
#pragma unroll
    for (int c = lane; c < D_OUT; c += 32) {
        float v = hr[c];
        mu += v * __ldg(&wm[c]);
        xi += v * __ldg(&wx[c]);
    }
#pragma unroll
    for (int o = 16; o; o >>= 1) {
        mu += __shfl_xor_sync(0xFFFFFFFFu, mu, o);
        xi += __shfl_xor_sync(0xFFFFFFFFu, xi, o);
    }
    if (lane == 0) { g_mu[warp] = mu; g_xi[warp] = xi; }
}

// ---------------------------------------------------------------------------
// Kernel B: fused masked softmax + aggregation, tf32 mma.sync.
// out_i = elu( (sum_j adj_ij * exp(lrelu(mu_i+xi_j)) * h_j) / Z_i )
// Scores bounded (|e|<=~4) -> no max subtraction; masked terms exactly 0.
// CTA: 64 rows x 256 cols; 8 warps (2x4); warp tile 32x64 (2x8 m16n8k8 frags).
// Register-prefetch double buffering of adj/xi/H over j-tiles of 32.
// ---------------------------------------------------------------------------
#define BM 64
#define KT 32
#define NJT (N_NODES / KT)          // 256 j-tiles
#define HPAD 264                    // Hs row stride (conflict-free B frags)
#define PPAD 36                     // Pt row stride (conflict-free A frags)

__global__ __launch_bounds__(256, 1) void attn_agg(const int* __restrict__ adj,
                                                   float* __restrict__ out) {
    __shared__ float Hs[KT][HPAD];      // 33 KB
    __shared__ float Pt[BM][PPAD];      // 9 KB
    __shared__ float zbuf[BM][4];
    __shared__ float Zs[BM];

    const int tid  = threadIdx.x;
    const int lane = tid & 31;
    const int warp = tid >> 5;
    const int warp_m = warp >> 2;       // 0..1
    const int warp_n = warp & 3;        // 0..3
    const int i0 = blockIdx.x * BM;

    // P-generation role: row pr, cols [pjc, pjc+8) of each j-tile
    const int pr  = tid >> 2;           // 0..63
    const int pjc = (tid & 3) * 8;      // 0,8,16,24
    const float mu_r = g_mu[i0 + pr];
    const int4* __restrict__ arow =
        (const int4*)(adj + (size_t)(i0 + pr) * N_NODES);

    float acc[2][8][4];
#pragma unroll
    for (int m = 0; m < 2; m++)
#pragma unroll
        for (int n = 0; n < 8; n++)
#pragma unroll
            for (int q = 0; q < 4; q++) acc[m][n][q] = 0.f;
    float zpart = 0.f;

    // ---- Prefetch tile 0 ----
    int4   adjA = arow[pjc >> 2];
    int4   adjB = arow[(pjc >> 2) + 1];
    float4 xiA  = *(const float4*)&g_xi[pjc];
    float4 xiB  = *(const float4*)&g_xi[pjc + 4];
    float4 hreg[8];
#pragma unroll
    for (int t = 0; t < 8; t++) {
        int lin = tid + t * 256;
        int k = lin >> 6, cv = lin & 63;
        hreg[t] = *(const float4*)&g_ht[(size_t)k * D_OUT + cv * 4];
    }

    for (int jt = 0; jt < NJT; jt++) {
        __syncthreads();   // previous tile's consumers done
        // ---- Write phase: P (masked exp, tf32-rounded) + H into smem ----
        {
            float xs[8] = {xiA.x, xiA.y, xiA.z, xiA.w,
                           xiB.x, xiB.y, xiB.z, xiB.w};
            int   am[8] = {adjA.x, adjA.y, adjA.z, adjA.w,
                           adjB.x, adjB.y, adjB.z, adjB.w};
#pragma unroll
            for (int kk = 0; kk < 8; kk++) {
                float e = mu_r + xs[kk];
                e = (e >= 0.f) ? e : (ALPHA * e);
                float p = (am[kk] > 0) ? __expf(e) : 0.f;
                p = to_tf32(p);
                Pt[pr][pjc + kk] = p;
                zpart += p;
            }
#pragma unroll
            for (int t = 0; t < 8; t++) {
                int lin = tid + t * 256;
                int k = lin >> 6, cv = lin & 63;
                *(float4*)&Hs[k][cv * 4] = hreg[t];
            }
        }
        __syncthreads();   // smem tile ready

        // ---- Prefetch next tile (LDGs overlap with mma below) ----
        if (jt + 1 < NJT) {
            int jn = (jt + 1) * KT;
            adjA = arow[(jn + pjc) >> 2];
            adjB = arow[((jn + pjc) >> 2) + 1];
            xiA  = *(const float4*)&g_xi[jn + pjc];
            xiB  = *(const float4*)&g_xi[jn + pjc + 4];
#pragma unroll
            for (int t = 0; t < 8; t++) {
                int lin = tid + t * 256;
                int k = lin >> 6, cv = lin & 63;
                hreg[t] = *(const float4*)&g_ht[(size_t)(jn + k) * D_OUT + cv * 4];
            }
        }

        // ---- MMA phase: acc[2][8] += P(32x32-slice) * H(32x64-slice) ----
#pragma unroll
        for (int ks = 0; ks < 4; ks++) {
            const int kk = ks * 8;
            uint32_t afr[2][4];
#pragma unroll
            for (int mt = 0; mt < 2; mt++) {
                int r0 = warp_m * 32 + mt * 16 + (lane >> 2);
                int kc = kk + (lane & 3);
                afr[mt][0] = __float_as_uint(Pt[r0][kc]);
                afr[mt][1] = __float_as_uint(Pt[r0 + 8][kc]);
                afr[mt][2] = __float_as_uint(Pt[r0][kc + 4]);
                afr[mt][3] = __float_as_uint(Pt[r0 + 8][kc + 4]);
            }
#pragma unroll
            for (int nt = 0; nt < 8; nt++) {
                int c  = warp_n * 64 + nt * 8 + (lane >> 2);
                int kr = kk + (lane & 3);
                uint32_t b0 = __float_as_uint(Hs[kr][c]);
                uint32_t b1 = __float_as_uint(Hs[kr + 4][c]);
                mma_tf32(acc[0][nt], afr[0], b0, b1);
                mma_tf32(acc[1][nt], afr[1], b0, b1);
            }
        }
    }

    // ---- Z reduction ----
    zbuf[pr][tid & 3] = zpart;
    __syncthreads();
    if (tid < BM)
        Zs[tid] = zbuf[tid][0] + zbuf[tid][1] + zbuf[tid][2] + zbuf[tid][3];
    __syncthreads();

    // ---- Epilogue: normalize + ELU, float2 stores ----
#pragma unroll
    for (int mt = 0; mt < 2; mt++) {
        int rA = warp_m * 32 + mt * 16 + (lane >> 2);
        int rB = rA + 8;
        float izA = 1.f / Zs[rA];
        float izB = 1.f / Zs[rB];
#pragma unroll
        for (int nt = 0; nt < 8; nt++) {
            int c = warp_n * 64 + nt * 8 + 2 * (lane & 3);
            float v0 = acc[mt][nt][0] * izA;
            float v1 = acc[mt][nt][1] * izA;
            float v2 = acc[mt][nt][2] * izB;
            float v3 = acc[mt][nt][3] * izB;
            float2 oA, oB;
            oA.x = (v0 > 0.f) ? v0 : (__expf(v0) - 1.f);
            oA.y = (v1 > 0.f) ? v1 : (__expf(v1) - 1.f);
            oB.x = (v2 > 0.f) ? v2 : (__expf(v2) - 1.f);
            oB.y = (v3 > 0.f) ? v3 : (__expf(v3) - 1.f);
            *(float2*)&out[(size_t)(i0 + rA) * D_OUT + c] = oA;
            *(float2*)&out[(size_t)(i0 + rB) * D_OUT + c] = oB;
        }
    }
}

// ---------------------------------------------------------------------------
extern "C" void kernel_launch(void* const* d_in, const int* in_sizes, int n_in,
                              void* d_out, int out_size) {
    const float* features = (const float*)d_in[0];
    const int*   adj      = (const int*)d_in[1];
    const float* W_phi    = (const float*)d_in[2];
    const float* w_mu     = (const float*)d_in[3];
    const float* w_xi     = (const float*)d_in[4];
    float* out = (float*)d_out;

    (void)in_sizes; (void)n_in; (void)out_size;

    dim3 gA(N_NODES / 64, D_OUT / 64);
    gemm_xw<<<gA, 256>>>(features, W_phi);

    mu_xi_kernel<<<(N_NODES * 32) / 256, 256>>>(w_mu, w_xi);

    attn_agg<<<N_NODES / BM, 256>>>(adj, out);
}

// round 9
// speedup vs baseline: 2.5722x; 1.1248x over previous
#include <cuda_runtime.h>
#include <cstdint>

#define N_NODES 8192
#define D_IN    512
#define D_OUT   256
#define ALPHA   0.2f

// Scratch (allocation-free rule: __device__ globals)
__device__ float g_h  [N_NODES * D_OUT];   // fp32 h (for mu/xi)
__device__ float g_ht [N_NODES * D_OUT];   // tf32-rounded h (mma B operand)
__device__ float g_emu[N_NODES];           // exp(mu_i)
__device__ float g_fmu[N_NODES];           // exp(ALPHA*mu_i)
__device__ float g_exf[2 * N_NODES];       // interleaved (exp(xi_j), exp(ALPHA*xi_j))

__device__ __forceinline__ float to_tf32(float x) {
    uint32_t u;
    asm("cvt.rna.tf32.f32 %0, %1;" : "=r"(u) : "f"(x));
    return __uint_as_float(u);
}

__device__ __forceinline__ uint32_t smem_u32(const void* p) {
    uint32_t a;
    asm("{ .reg .u64 t; cvta.to.shared.u64 t, %1; cvt.u32.u64 %0, t; }"
        : "=r"(a) : "l"(p));
    return a;
}

__device__ __forceinline__ void mma_tf32(float c[4], const uint32_t a[4],
                                         uint32_t b0, uint32_t b1) {
    asm volatile(
        "mma.sync.aligned.m16n8k8.row.col.f32.tf32.tf32.f32 "
        "{%0,%1,%2,%3}, {%4,%5,%6,%7}, {%8,%9}, {%0,%1,%2,%3};"
        : "+f"(c[0]), "+f"(c[1]), "+f"(c[2]), "+f"(c[3])
        : "r"(a[0]), "r"(a[1]), "r"(a[2]), "r"(a[3]), "r"(b0), "r"(b1));
}

#define CP_ASYNC16(dst, src) \
    asm volatile("cp.async.cg.shared.global [%0], [%1], 16;" :: "r"(dst), "l"(src) : "memory")
#define CP_ASYNC_WAIT_ALL() \
    asm volatile("cp.async.wait_all;" ::: "memory")

// ---------------------------------------------------------------------------
// Kernel A: h = X[8192,512] @ W[512,256]  (fp32, tiled 64x64, 4x4 microtiles)
// Epilogue writes fp32 g_h and tf32-rounded g_ht.
// ---------------------------------------------------------------------------
__global__ __launch_bounds__(256) void gemm_xw(const float* __restrict__ X,
                                               const float* __restrict__ W) {
    __shared__ float Xst[32][64];
    __shared__ float Ws[32][64];
    const int tid = threadIdx.x;
    const int i0 = blockIdx.x * 64;
    const int c0 = blockIdx.y * 64;
    const int r_local = (tid / 16) * 4;
    const int c_local = (tid % 16) * 4;

    float acc[4][4];
#pragma unroll
    for (int a = 0; a < 4; a++)
#pragma unroll
        for (int b = 0; b < 4; b++) acc[a][b] = 0.f;

    for (int k0 = 0; k0 < D_IN; k0 += 32) {
        __syncthreads();
#pragma unroll
        for (int t = 0; t < 2; t++) {
            int lin = tid + t * 256;
            int r = lin / 8, kv = lin % 8;
            float4 v = *(const float4*)&X[(i0 + r) * D_IN + k0 + kv * 4];
            Xst[kv * 4 + 0][r] = v.x;
            Xst[kv * 4 + 1][r] = v.y;
            Xst[kv * 4 + 2][r] = v.z;
            Xst[kv * 4 + 3][r] = v.w;
        }
#pragma unroll
        for (int t = 0; t < 2; t++) {
            int lin = tid + t * 256;
            int k = lin / 16, cv = lin % 16;
            *(float4*)&Ws[k][cv * 4] =
                *(const float4*)&W[(k0 + k) * D_OUT + c0 + cv * 4];
        }
        __syncthreads();
#pragma unroll
        for (int k = 0; k < 32; k++) {
            float4 a4 = *(const float4*)&Xst[k][r_local];
            float4 b4 = *(const float4*)&Ws[k][c_local];
            float av[4] = {a4.x, a4.y, a4.z, a4.w};
            float bv[4] = {b4.x, b4.y, b4.z, b4.w};
#pragma unroll
            for (int i = 0; i < 4; i++)
#pragma unroll
                for (int j = 0; j < 4; j++) acc[i][j] += av[i] * bv[j];
        }
    }
#pragma unroll
    for (int i = 0; i < 4; i++) {
        int idx = (i0 + r_local + i) * D_OUT + c0 + c_local;
        float4 o = make_float4(acc[i][0], acc[i][1], acc[i][2], acc[i][3]);
        *(float4*)&g_h[idx] = o;
        float4 ot = make_float4(to_tf32(o.x), to_tf32(o.y),
                                to_tf32(o.z), to_tf32(o.w));
        *(float4*)&g_ht[idx] = ot;
    }
}

// ---------------------------------------------------------------------------
// Kernel A2: mu/xi dots + precomputed exp tables.
// Emu=exp(mu), Fmu=exp(.2mu); exf[j] = (exp(xi), exp(.2xi)) interleaved.
// ---------------------------------------------------------------------------
__global__ __launch_bounds__(256) void mu_xi_kernel(const float* __restrict__ wm,
                                                    const float* __restrict__ wx) {
    int warp = (blockIdx.x * blockDim.x + threadIdx.x) >> 5;
    int lane = threadIdx.x & 31;
    if (warp >= N_NODES) return;
    const float* hr = &g_h[warp * D_OUT];
    float mu = 0.f, xi = 0.f;
#pragma unroll
    for (int c = lane; c < D_OUT; c += 32) {
        float v = hr[c];
        mu += v * __ldg(&wm[c]);
        xi += v * __ldg(&wx[c]);
    }
#pragma unroll
    for (int o = 16; o; o >>= 1) {
        mu += __shfl_xor_sync(0xFFFFFFFFu, mu, o);
        xi += __shfl_xor_sync(0xFFFFFFFFu, xi, o);
    }
    if (lane == 0) {
        g_emu[warp] = __expf(mu);
        g_fmu[warp] = __expf(ALPHA * mu);
        g_exf[2 * warp]     = __expf(xi);
        g_exf[2 * warp + 1] = __expf(ALPHA * xi);
    }
}

// ---------------------------------------------------------------------------
// Kernel B: fused masked softmax + aggregation, tf32 mma.sync, MUFU-free.
// p_ij = adj ? (Emu_i*Exi_j >= 1 ? Emu_i*Exi_j : Fmu_i*Fxi_j) : 0
// CTA: 64 rows x 256 cols; 8 warps (2x4); warp tile 32x64 (2x8 m16n8k8).
// Double-buffered smem (Pt/Hs), ONE barrier per tile; H via cp.async.
// ---------------------------------------------------------------------------
#define BM 64
#define KT 32
#define NJT (N_NODES / KT)
#define HPAD 264
#define PPAD 36
#define HS_F (KT * HPAD)            // floats per H buffer
#define PT_F (BM * PPAD)            // floats per P buffer
#define SM_FLOATS (2 * HS_F + 2 * PT_F + BM * 4 + BM)
#define SM_BYTES  (SM_FLOATS * 4)

__global__ __launch_bounds__(256, 1) void attn_agg(const int* __restrict__ adj,
                                                   float* __restrict__ out) {
    extern __shared__ float sm[];
    float* HsF  = sm;                       // [2][KT][HPAD]
    float* PtF  = sm + 2 * HS_F;            // [2][BM][PPAD]
    float* zbuf = PtF + 2 * PT_F;           // [BM][4]
    float* Zs   = zbuf + BM * 4;            // [BM]
    const uint32_t hs_base = smem_u32(HsF);

    const int tid  = threadIdx.x;
    const int lane = tid & 31;
    const int warp = tid >> 5;
    const int warp_m = warp >> 2;           // 0..1
    const int warp_n = warp & 3;            // 0..3
    const int i0 = blockIdx.x * BM;

    // producer role: row pr, j-cols [pjc, pjc+8)
    const int pr  = tid >> 2;               // 0..63
    const int pjc = (tid & 3) * 8;          // 0,8,16,24
    const float emu_r = g_emu[i0 + pr];
    const float fmu_r = g_fmu[i0 + pr];
    const int4* __restrict__ arow =
        (const int4*)(adj + (size_t)(i0 + pr) * N_NODES);

    float acc[2][8][4];
#pragma unroll
    for (int m = 0; m < 2; m++)
#pragma unroll
        for (int n = 0; n < 8; n++)
#pragma unroll
            for (int q = 0; q < 4; q++) acc[m][n][q] = 0.f;
    float zpart = 0.f;

    // ---- helpers as lambdas ----
    auto write_P = [&](int buf, int4 aA, int4 aB, const float4 ef[4]) {
        int   am[8] = {aA.x, aA.y, aA.z, aA.w, aB.x, aB.y, aB.z, aB.w};
        float p[8];
        float z = 0.f;
#pragma unroll
        for (int q = 0; q < 4; q++) {
            float ge0 = emu_r * ef[q].x;    // j = pjc+2q
            float fe0 = fmu_r * ef[q].y;
            float ge1 = emu_r * ef[q].z;    // j = pjc+2q+1
            float fe1 = fmu_r * ef[q].w;
            float v0 = (ge0 >= 1.f) ? ge0 : fe0;
            float v1 = (ge1 >= 1.f) ? ge1 : fe1;
            v0 = (am[2 * q] > 0) ? to_tf32(v0) : 0.f;
            v1 = (am[2 * q + 1] > 0) ? to_tf32(v1) : 0.f;
            p[2 * q] = v0; p[2 * q + 1] = v1;
            z += v0 + v1;
        }
        float* dst = &PtF[buf * PT_F + pr * PPAD + pjc];
        *(float4*)&dst[0] = make_float4(p[0], p[1], p[2], p[3]);
        *(float4*)&dst[4] = make_float4(p[4], p[5], p[6], p[7]);
        return z;
    };

    auto issue_H = [&](int buf, int j0) {
#pragma unroll
        for (int t = 0; t < 8; t++) {
            int lin = tid + t * 256;        // 0..2047 (16B chunks)
            int k = lin >> 6, cv = lin & 63;
            uint32_t dst = hs_base +
                (uint32_t)(buf * HS_F + k * HPAD + cv * 4) * 4u;
            CP_ASYNC16(dst, &g_ht[(size_t)(j0 + k) * D_OUT + cv * 4]);
        }
    };

    // ---- Prologue: tile 0 -> buf 0; prefetch tile-1 regs ----
    int4   aA = arow[pjc >> 2];
    int4   aB = arow[(pjc >> 2) + 1];
    float4 ef[4];
#pragma unroll
    for (int q = 0; q < 4; q++)
        ef[q] = *(const float4*)&g_exf[2 * pjc + q * 4];
    issue_H(0, 0);
    zpart += write_P(0, aA, aB, ef);
    aA = arow[(KT + pjc) >> 2];
    aB = arow[((KT + pjc) >> 2) + 1];
#pragma unroll
    for (int q = 0; q < 4; q++)
        ef[q] = *(const float4*)&g_exf[2 * (KT + pjc) + q * 4];
    CP_ASYNC_WAIT_ALL();
    __syncthreads();

    for (int jt = 0; jt < NJT; jt++) {
        const int buf = jt & 1;
        const int nbuf = buf ^ 1;

        // ---- produce tile jt+1 into nbuf (cp.async first, then P) ----
        if (jt + 1 < NJT) {
            issue_H(nbuf, (jt + 1) * KT);
            zpart += write_P(nbuf, aA, aB, ef);
            if (jt + 2 < NJT) {
                int j2 = (jt + 2) * KT;
                aA = arow[(j2 + pjc) >> 2];
                aB = arow[((j2 + pjc) >> 2) + 1];
#pragma unroll
                for (int q = 0; q < 4; q++)
                    ef[q] = *(const float4*)&g_exf[2 * (j2 + pjc) + q * 4];
            }
        }

        // ---- MMA on buf ----
        {
            const float* PtB = &PtF[buf * PT_F];
            const float* HsB = &HsF[buf * HS_F];
#pragma unroll
            for (int ks = 0; ks < 4; ks++) {
                const int kk = ks * 8;
                uint32_t afr[2][4];
#pragma unroll
                for (int mt = 0; mt < 2; mt++) {
                    int r0 = warp_m * 32 + mt * 16 + (lane >> 2);
                    int kc = kk + (lane & 3);
                    afr[mt][0] = __float_as_uint(PtB[r0 * PPAD + kc]);
                    afr[mt][1] = __float_as_uint(PtB[(r0 + 8) * PPAD + kc]);
                    afr[mt][2] = __float_as_uint(PtB[r0 * PPAD + kc + 4]);
                    afr[mt][3] = __float_as_uint(PtB[(r0 + 8) * PPAD + kc + 4]);
                }
#pragma unroll
                for (int nt = 0; nt < 8; nt++) {
                    int c  = warp_n * 64 + nt * 8 + (lane >> 2);
                    int kr = kk + (lane & 3);
                    uint32_t b0 = __float_as_uint(HsB[kr * HPAD + c]);
                    uint32_t b1 = __float_as_uint(HsB[(kr + 4) * HPAD + c]);
                    mma_tf32(acc[0][nt], afr[0], b0, b1);
                    mma_tf32(acc[1][nt], afr[1], b0, b1);
                }
            }
        }

        if (jt + 1 < NJT) CP_ASYNC_WAIT_ALL();
        __syncthreads();
    }

    // ---- Z reduction ----
    zbuf[pr * 4 + (tid & 3)] = zpart;
    __syncthreads();
    if (tid < BM)
        Zs[tid] = zbuf[tid * 4] + zbuf[tid * 4 + 1] +
                  zbuf[tid * 4 + 2] + zbuf[tid * 4 + 3];
    __syncthreads();

    // ---- Epilogue: normalize + ELU ----
#pragma unroll
    for (int mt = 0; mt < 2; mt++) {
        int rA = warp_m * 32 + mt * 16 + (lane >> 2);
        int rB = rA + 8;
        float izA = 1.f / Zs[rA];
        float izB = 1.f / Zs[rB];
#pragma unroll
        for (int nt = 0; nt < 8; nt++) {
            int c = warp_n * 64 + nt * 8 + 2 * (lane & 3);
            float v0 = acc[mt][nt][0] * izA;
            float v1 = acc[mt][nt][1] * izA;
            float v2 = acc[mt][nt][2] * izB;
            float v3 = acc[mt][nt][3] * izB;
            float2 oA, oB;
            oA.x = (v0 > 0.f) ? v0 : (__expf(v0) - 1.f);
            oA.y = (v1 > 0.f) ? v1 : (__expf(v1) - 1.f);
            oB.x = (v2 > 0.f) ? v2 : (__expf(v2) - 1.f);
            oB.y = (v3 > 0.f) ? v3 : (__expf(v3) - 1.f);
            *(float2*)&out[(size_t)(i0 + rA) * D_OUT + c] = oA;
            *(float2*)&out[(size_t)(i0 + rB) * D_OUT + c] = oB;
        }
    }
}

// ---------------------------------------------------------------------------
extern "C" void kernel_launch(void* const* d_in, const int* in_sizes, int n_in,
                              void* d_out, int out_size) {
    const float* features = (const float*)d_in[0];
    const int*   adj      = (const int*)d_in[1];
    const float* W_phi    = (const float*)d_in[2];
    const float* w_mu     = (const float*)d_in[3];
    const float* w_xi     = (const float*)d_in[4];
    float* out = (float*)d_out;

    (void)in_sizes; (void)n_in; (void)out_size;

    dim3 gA(N_NODES / 64, D_OUT / 64);
    gemm_xw<<<gA, 256>>>(features, W_phi);

    mu_xi_kernel<<<(N_NODES * 32) / 256, 256>>>(w_mu, w_xi);

    cudaFuncSetAttribute(attn_agg, cudaFuncAttributeMaxDynamicSharedMemorySize,
                         SM_BYTES);
    attn_agg<<<N_NODES / BM, 256, SM_BYTES>>>(adj, out);
}

// round 10
// speedup vs baseline: 2.8908x; 1.1239x over previous
#include <cuda_runtime.h>
#include <cuda_fp16.h>
#include <cstdint>

#define N_NODES 8192
#define D_IN    512
#define D_OUT   256
#define ALPHA   0.2f

// Scratch (allocation-free rule: __device__ globals)
__device__ float  g_h  [N_NODES * D_OUT];   // fp32 h (for mu/xi)
__device__ __half g_htT[D_OUT * N_NODES];   // transposed fp16 h: [c][j] (B operand)
__device__ float  g_emu[N_NODES];           // exp(mu_i)
__device__ float  g_fmu[N_NODES];           // exp(ALPHA*mu_i)
__device__ float  g_exf[2 * N_NODES];       // interleaved (exp(xi_j), exp(ALPHA*xi_j))

__device__ __forceinline__ uint32_t smem_u32(const void* p) {
    uint32_t a;
    asm("{ .reg .u64 t; cvta.to.shared.u64 t, %1; cvt.u32.u64 %0, t; }"
        : "=r"(a) : "l"(p));
    return a;
}

__device__ __forceinline__ void mma_f16(float c[4], const uint32_t a[4],
                                        uint32_t b0, uint32_t b1) {
    asm volatile(
        "mma.sync.aligned.m16n8k16.row.col.f32.f16.f16.f32 "
        "{%0,%1,%2,%3}, {%4,%5,%6,%7}, {%8,%9}, {%0,%1,%2,%3};"
        : "+f"(c[0]), "+f"(c[1]), "+f"(c[2]), "+f"(c[3])
        : "r"(a[0]), "r"(a[1]), "r"(a[2]), "r"(a[3]), "r"(b0), "r"(b1));
}

#define CP_ASYNC16(dst, src) \
    asm volatile("cp.async.cg.shared.global [%0], [%1], 16;" :: "r"(dst), "l"(src) : "memory")
#define CP_ASYNC_WAIT_ALL() \
    asm volatile("cp.async.wait_all;" ::: "memory")

// ---------------------------------------------------------------------------
// Kernel A: h = X[8192,512] @ W[512,256]  (fp32, tiled 64x64, 4x4 microtiles)
// Epilogue writes fp32 g_h and the TRANSPOSED fp16 g_htT[c][i] (smem bounce).
// ---------------------------------------------------------------------------
__global__ __launch_bounds__(256) void gemm_xw(const float* __restrict__ X,
                                               const float* __restrict__ W) {
    __shared__ float Xst[32][64];
    __shared__ float Ws[32][64];
    __shared__ float Tr[64][65];
    const int tid = threadIdx.x;
    const int i0 = blockIdx.x * 64;
    const int c0 = blockIdx.y * 64;
    const int r_local = (tid / 16) * 4;
    const int c_local = (tid % 16) * 4;

    float acc[4][4];
#pragma unroll
    for (int a = 0; a < 4; a++)
#pragma unroll
        for (int b = 0; b < 4; b++) acc[a][b] = 0.f;

    for (int k0 = 0; k0 < D_IN; k0 += 32) {
        __syncthreads();
#pragma unroll
        for (int t = 0; t < 2; t++) {
            int lin = tid + t * 256;
            int r = lin / 8, kv = lin % 8;
            float4 v = *(const float4*)&X[(i0 + r) * D_IN + k0 + kv * 4];
            Xst[kv * 4 + 0][r] = v.x;
            Xst[kv * 4 + 1][r] = v.y;
            Xst[kv * 4 + 2][r] = v.z;
            Xst[kv * 4 + 3][r] = v.w;
        }
#pragma unroll
        for (int t = 0; t < 2; t++) {
            int lin = tid + t * 256;
            int k = lin / 16, cv = lin % 16;
            *(float4*)&Ws[k][cv * 4] =
                *(const float4*)&W[(k0 + k) * D_OUT + c0 + cv * 4];
        }
        __syncthreads();
#pragma unroll
        for (int k = 0; k < 32; k++) {
            float4 a4 = *(const float4*)&Xst[k][r_local];
            float4 b4 = *(const float4*)&Ws[k][c_local];
            float av[4] = {a4.x, a4.y, a4.z, a4.w};
            float bv[4] = {b4.x, b4.y, b4.z, b4.w};
#pragma unroll
            for (int i = 0; i < 4; i++)
#pragma unroll
                for (int j = 0; j < 4; j++) acc[i][j] += av[i] * bv[j];
        }
    }
#pragma unroll
    for (int i = 0; i < 4; i++) {
        int row = i0 + r_local + i;
        *(float4*)&g_h[row * D_OUT + c0 + c_local] =
            make_float4(acc[i][0], acc[i][1], acc[i][2], acc[i][3]);
#pragma unroll
        for (int j = 0; j < 4; j++)
            Tr[c_local + j][r_local + i] = acc[i][j];
    }
    __syncthreads();
    // coalesced transposed fp16 store: thread t -> c = t/4, 16-half chunk q = t%4
    {
        int c = tid >> 2, q = tid & 3;
        __half hbuf[16];
#pragma unroll
        for (int v = 0; v < 16; v++)
            hbuf[v] = __float2half_rn(Tr[c][q * 16 + v]);
        __half* dst = &g_htT[(size_t)(c0 + c) * N_NODES + i0 + q * 16];
        *(uint4*)&dst[0] = *(const uint4*)&hbuf[0];
        *(uint4*)&dst[8] = *(const uint4*)&hbuf[8];
    }
}

// ---------------------------------------------------------------------------
// Kernel A2: mu/xi dots + precomputed exp tables.
// ---------------------------------------------------------------------------
__global__ __launch_bounds__(256) void mu_xi_kernel(const float* __restrict__ wm,
                                                    const float* __restrict__ wx) {
    int warp = (blockIdx.x * blockDim.x + threadIdx.x) >> 5;
    int lane = threadIdx.x & 31;
    if (warp >= N_NODES) return;
    const float* hr = &g_h[warp * D_OUT];
    float mu = 0.f, xi = 0.f;
#pragma unroll
    for (int c = lane; c < D_OUT; c += 32) {
        float v = hr[c];
        mu += v * __ldg(&wm[c]);
        xi += v * __ldg(&wx[c]);
    }
#pragma unroll
    for (int o = 16; o; o >>= 1) {
        mu += __shfl_xor_sync(0xFFFFFFFFu, mu, o);
        xi += __shfl_xor_sync(0xFFFFFFFFu, xi, o);
    }
    if (lane == 0) {
        g_emu[warp] = __expf(mu);
        g_fmu[warp] = __expf(ALPHA * mu);
        g_exf[2 * warp]     = __expf(xi);
        g_exf[2 * warp + 1] = __expf(ALPHA * xi);
    }
}

// ---------------------------------------------------------------------------
// Kernel B: fused masked softmax + aggregation, fp16 m16n8k16 mma, MUFU-free.
// p_ij = adj ? (Emu_i*Exi_j >= 1 ? Emu_i*Exi_j : Fmu_i*Fxi_j) : 0   (fp16-rnd)
// CTA: 64 rows x 256 cols, 512 threads, 16 warps (2x8), warp tile 32x32.
// P tile [64r][32k] fp16 stride 80B; H tile [256c][32k] fp16 stride 80B
// (both conflict-free for fragment loads). Double-buffered, 1 barrier/tile.
// ---------------------------------------------------------------------------
#define BM 64
#define KT 32
#define NJT (N_NODES / KT)
#define PT_STRIDE 80
#define PT_BYTES  (BM * PT_STRIDE)          // 5120
#define HS_STRIDE 80
#define HS_BYTES  (D_OUT * HS_STRIDE)       // 20480
#define PT_OFF    0
#define HS_OFF    (2 * PT_BYTES)            // 10240
#define ZB_OFF    (HS_OFF + 2 * HS_BYTES)   // 51200
#define ZS_OFF    (ZB_OFF + BM * 8 * 4)     // 53248
#define SM_BYTES  (ZS_OFF + BM * 4)         // 53504

__global__ __launch_bounds__(512, 1) void attn_agg(const int* __restrict__ adj,
                                                   float* __restrict__ out) {
    extern __shared__ char sm[];
    const uint32_t base = smem_u32(sm);
    float* zbuf = (float*)(sm + ZB_OFF);
    float* Zs   = (float*)(sm + ZS_OFF);

    const int tid  = threadIdx.x;
    const int lane = tid & 31;
    const int warp = tid >> 5;
    const int warp_m = warp >> 3;           // 0..1
    const int warp_n = warp & 7;            // 0..7
    const int i0 = blockIdx.x * BM;

    // producer role: row pr (0..63), 4 j's at pjc = (tid&7)*4
    const int pr  = tid >> 3;
    const int pjc = (tid & 7) * 4;
    const float emu_r = g_emu[i0 + pr];
    const float fmu_r = g_fmu[i0 + pr];
    const int4* __restrict__ arow =
        (const int4*)(adj + (size_t)(i0 + pr) * N_NODES);

    float acc[2][4][4];
#pragma unroll
    for (int m = 0; m < 2; m++)
#pragma unroll
        for (int n = 0; n < 4; n++)
#pragma unroll
            for (int q = 0; q < 4; q++) acc[m][n][q] = 0.f;
    float zpart = 0.f;

    auto write_P = [&](int buf, int4 am4, float4 e0, float4 e1) {
        int am[4] = {am4.x, am4.y, am4.z, am4.w};
        float es[8] = {e0.x, e0.y, e0.z, e0.w, e1.x, e1.y, e1.z, e1.w};
        __half hp[4];
        float z = 0.f;
#pragma unroll
        for (int q = 0; q < 4; q++) {
            float ge = emu_r * es[2 * q];
            float fe = fmu_r * es[2 * q + 1];
            float v = (ge >= 1.f) ? ge : fe;
            __half hv = (am[q] > 0) ? __float2half_rn(v) : __half(0.f);
            hp[q] = hv;
            z += __half2float(hv);
        }
        char* dst = sm + PT_OFF + buf * PT_BYTES + pr * PT_STRIDE + pjc * 2;
        *(uint2*)dst = *(const uint2*)hp;
        return z;
    };

    auto issue_H = [&](int buf, int j0) {
#pragma unroll
        for (int t = 0; t < 2; t++) {
            int lin = tid + t * 512;        // 0..1023
            int c = lin >> 2, q = lin & 3;
            uint32_t dst = base + HS_OFF + buf * HS_BYTES +
                           (uint32_t)(c * HS_STRIDE + q * 16);
            CP_ASYNC16(dst, &g_htT[(size_t)c * N_NODES + j0 + q * 8]);
        }
    };

    // ---- Prologue: tile 0 -> buf 0; prefetch tile-1 regs ----
    int4   aA = arow[pjc >> 2];
    float4 ef0 = *(const float4*)&g_exf[2 * pjc];
    float4 ef1 = *(const float4*)&g_exf[2 * pjc + 4];
    issue_H(0, 0);
    zpart += write_P(0, aA, ef0, ef1);
    aA  = arow[(KT + pjc) >> 2];
    ef0 = *(const float4*)&g_exf[2 * (KT + pjc)];
    ef1 = *(const float4*)&g_exf[2 * (KT + pjc) + 4];
    CP_ASYNC_WAIT_ALL();
    __syncthreads();

    for (int jt = 0; jt < NJT; jt++) {
        const int buf = jt & 1;
        const int nbuf = buf ^ 1;

        // ---- produce tile jt+1 into nbuf ----
        if (jt + 1 < NJT) {
            issue_H(nbuf, (jt + 1) * KT);
            zpart += write_P(nbuf, aA, ef0, ef1);
            if (jt + 2 < NJT) {
                int j2 = (jt + 2) * KT;
                aA  = arow[(j2 + pjc) >> 2];
                ef0 = *(const float4*)&g_exf[2 * (j2 + pjc)];
                ef1 = *(const float4*)&g_exf[2 * (j2 + pjc) + 4];
            }
        }

        // ---- MMA on buf: 2 k-steps of 16 ----
        {
            const char* PtB = sm + PT_OFF + buf * PT_BYTES;
            const char* HsB = sm + HS_OFF + buf * HS_BYTES;
#pragma unroll
            for (int ks = 0; ks < 2; ks++) {
                uint32_t afr[2][4];
#pragma unroll
                for (int mt = 0; mt < 2; mt++) {
                    int r0 = warp_m * 32 + mt * 16 + (lane >> 2);
                    const char* pa = PtB + r0 * PT_STRIDE + ks * 32 + (lane & 3) * 4;
                    afr[mt][0] = *(const uint32_t*)pa;
                    afr[mt][1] = *(const uint32_t*)(pa + 8 * PT_STRIDE);
                    afr[mt][2] = *(const uint32_t*)(pa + 16);
                    afr[mt][3] = *(const uint32_t*)(pa + 8 * PT_STRIDE + 16);
                }
#pragma unroll
                for (int nt = 0; nt < 4; nt++) {
                    int c = warp_n * 32 + nt * 8 + (lane >> 2);
                    const char* pb = HsB + c * HS_STRIDE + ks * 32 + (lane & 3) * 4;
                    uint32_t b0 = *(const uint32_t*)pb;
                    uint32_t b1 = *(const uint32_t*)(pb + 16);
                    mma_f16(acc[0][nt], afr[0], b0, b1);
                    mma_f16(acc[1][nt], afr[1], b0, b1);
                }
            }
        }

        if (jt + 1 < NJT) CP_ASYNC_WAIT_ALL();
        __syncthreads();
    }

    // ---- Z reduction ----
    zbuf[pr * 8 + (tid & 7)] = zpart;
    __syncthreads();
    if (tid < BM) {
        float s = 0.f;
#pragma unroll
        for (int t = 0; t < 8; t++) s += zbuf[tid * 8 + t];
        Zs[tid] = s;
    }
    __syncthreads();

    // ---- Epilogue: normalize + ELU ----
#pragma unroll
    for (int mt = 0; mt < 2; mt++) {
        int rA = warp_m * 32 + mt * 16 + (lane >> 2);
        int rB = rA + 8;
        float izA = 1.f / Zs[rA];
        float izB = 1.f / Zs[rB];
#pragma unroll
        for (int nt = 0; nt < 4; nt++) {
            int c = warp_n * 32 + nt * 8 + 2 * (lane & 3);
            float v0 = acc[mt][nt][0] * izA;
            float v1 = acc[mt][nt][1] * izA;
            float v2 = acc[mt][nt][2] * izB;
            float v3 = acc[mt][nt][3] * izB;
            float2 oA, oB;
            oA.x = (v0 > 0.f) ? v0 : (__expf(v0) - 1.f);
            oA.y = (v1 > 0.f) ? v1 : (__expf(v1) - 1.f);
            oB.x = (v2 > 0.f) ? v2 : (__expf(v2) - 1.f);
            oB.y = (v3 > 0.f) ? v3 : (__expf(v3) - 1.f);
            *(float2*)&out[(size_t)(i0 + rA) * D_OUT + c] = oA;
            *(float2*)&out[(size_t)(i0 + rB) * D_OUT + c] = oB;
        }
    }
}

// ---------------------------------------------------------------------------
extern "C" void kernel_launch(void* const* d_in, const int* in_sizes, int n_in,
                              void* d_out, int out_size) {
    const float* features = (const float*)d_in[0];
    const int*   adj      = (const int*)d_in[1];
    const float* W_phi    = (const float*)d_in[2];
    const float* w_mu     = (const float*)d_in[3];
    const float* w_xi     = (const float*)d_in[4];
    float* out = (float*)d_out;

    (void)in_sizes; (void)n_in; (void)out_size;

    dim3 gA(N_NODES / 64, D_OUT / 64);
    gemm_xw<<<gA, 256>>>(features, W_phi);

    mu_xi_kernel<<<(N_NODES * 32) / 256, 256>>>(w_mu, w_xi);

    cudaFuncSetAttribute(attn_agg, cudaFuncAttributeMaxDynamicSharedMemorySize,
                         SM_BYTES);
    attn_agg<<<N_NODES / BM, 512, SM_BYTES>>>(adj, out);
}

// round 11
// speedup vs baseline: 3.2769x; 1.1335x over previous
#include <cuda_runtime.h>
#include <cuda_fp16.h>
#include <cstdint>

#define N_NODES 8192
#define D_IN    512
#define D_OUT   256
#define ALPHA   0.2f

// Scratch (allocation-free rule: __device__ globals)
__device__ float  g_h  [N_NODES * D_OUT];   // fp32 h (for mu/xi)
__device__ __half g_htT[D_OUT * N_NODES];   // transposed fp16 h: [c][j] (B operand)
__device__ float  g_emu[N_NODES];           // exp(mu_i)
__device__ float  g_fmu[N_NODES];           // exp(ALPHA*mu_i)
__device__ float  g_exf[2 * N_NODES];       // interleaved (exp(xi_j), exp(ALPHA*xi_j))

__device__ __forceinline__ float to_tf32(float x) {
    uint32_t u;
    asm("cvt.rna.tf32.f32 %0, %1;" : "=r"(u) : "f"(x));
    return __uint_as_float(u);
}

__device__ __forceinline__ uint32_t smem_u32(const void* p) {
    uint32_t a;
    asm("{ .reg .u64 t; cvta.to.shared.u64 t, %1; cvt.u32.u64 %0, t; }"
        : "=r"(a) : "l"(p));
    return a;
}

__device__ __forceinline__ void mma_f16(float c[4], const uint32_t a[4],
                                        uint32_t b0, uint32_t b1) {
    asm volatile(
        "mma.sync.aligned.m16n8k16.row.col.f32.f16.f16.f32 "
        "{%0,%1,%2,%3}, {%4,%5,%6,%7}, {%8,%9}, {%0,%1,%2,%3};"
        : "+f"(c[0]), "+f"(c[1]), "+f"(c[2]), "+f"(c[3])
        : "r"(a[0]), "r"(a[1]), "r"(a[2]), "r"(a[3]), "r"(b0), "r"(b1));
}

__device__ __forceinline__ void mma_tf32(float c[4], const uint32_t a[4],
                                         uint32_t b0, uint32_t b1) {
    asm volatile(
        "mma.sync.aligned.m16n8k8.row.col.f32.tf32.tf32.f32 "
        "{%0,%1,%2,%3}, {%4,%5,%6,%7}, {%8,%9}, {%0,%1,%2,%3};"
        : "+f"(c[0]), "+f"(c[1]), "+f"(c[2]), "+f"(c[3])
        : "r"(a[0]), "r"(a[1]), "r"(a[2]), "r"(a[3]), "r"(b0), "r"(b1));
}

#define LDSM_X4(r, addr) \
    asm volatile("ldmatrix.sync.aligned.m8n8.x4.shared.b16 {%0,%1,%2,%3}, [%4];" \
                 : "=r"((r)[0]), "=r"((r)[1]), "=r"((r)[2]), "=r"((r)[3]) \
                 : "r"(addr))

#define CP_ASYNC16(dst, src) \
    asm volatile("cp.async.cg.shared.global [%0], [%1], 16;" :: "r"(dst), "l"(src) : "memory")
#define CP_ASYNC_WAIT_ALL() \
    asm volatile("cp.async.wait_all;" ::: "memory")

// ---------------------------------------------------------------------------
// Kernel A: h = X[8192,512] @ W[512,256] via tf32 mma.sync (fp32 accum).
// X/W rna-rounded to tf32 during smem staging (bias-free).
// CTA 64x64, 8 warps (2x4), warp tile 32x16 (2x2 m16n8k8 frags).
// Epilogue: fp32 g_h + transposed fp16 g_htT (smem bounce, coalesced).
// ---------------------------------------------------------------------------
__global__ __launch_bounds__(256) void gemm_xw(const float* __restrict__ X,
                                               const float* __restrict__ W) {
    __shared__ float pool[4608];
    float (*Xs)[36] = (float(*)[36])pool;           // [64][36]
    float (*Ws)[72] = (float(*)[72])(pool + 2304);  // [32][72]
    const int tid  = threadIdx.x;
    const int lane = tid & 31;
    const int wid  = tid >> 5;
    const int warp_m = wid >> 2;    // 0..1 -> 32 rows
    const int warp_n = wid & 3;     // 0..3 -> 16 cols
    const int i0 = blockIdx.x * 64;
    const int c0 = blockIdx.y * 64;

    float acc[2][2][4];
#pragma unroll
    for (int m = 0; m < 2; m++)
#pragma unroll
        for (int n = 0; n < 2; n++)
#pragma unroll
            for (int q = 0; q < 4; q++) acc[m][n][q] = 0.f;

    for (int k0 = 0; k0 < D_IN; k0 += 32) {
        __syncthreads();
        // stage X tile 64x32 (rna -> tf32)
#pragma unroll
        for (int s = 0; s < 2; s++) {
            int lin = tid + s * 256;
            int r = lin >> 3, q = lin & 7;
            float4 v = *(const float4*)&X[(size_t)(i0 + r) * D_IN + k0 + q * 4];
            v.x = to_tf32(v.x); v.y = to_tf32(v.y);
            v.z = to_tf32(v.z); v.w = to_tf32(v.w);
            *(float4*)&Xs[r][q * 4] = v;
        }
        // stage W tile 32x64 (rna -> tf32), layout [k][n]
#pragma unroll
        for (int s = 0; s < 2; s++) {
            int lin = tid + s * 256;
            int r = lin >> 4, q = lin & 15;
            float4 v = *(const float4*)&W[(size_t)(k0 + r) * D_OUT + c0 + q * 4];
            v.x = to_tf32(v.x); v.y = to_tf32(v.y);
            v.z = to_tf32(v.z); v.w = to_tf32(v.w);
            *(float4*)&Ws[r][q * 4] = v;
        }
        __syncthreads();
#pragma unroll
        for (int ks = 0; ks < 4; ks++) {
            const int kk = ks * 8;
            uint32_t afr[2][4];
#pragma unroll
            for (int mt = 0; mt < 2; mt++) {
                int r0 = warp_m * 32 + mt * 16 + (lane >> 2);
                int kc = kk + (lane & 3);
                afr[mt][0] = __float_as_uint(Xs[r0][kc]);
                afr[mt][1] = __float_as_uint(Xs[r0 + 8][kc]);
                afr[mt][2] = __float_as_uint(Xs[r0][kc + 4]);
                afr[mt][3] = __float_as_uint(Xs[r0 + 8][kc + 4]);
            }
#pragma unroll
            for (int nt = 0; nt < 2; nt++) {
                int cb = warp_n * 16 + nt * 8 + (lane >> 2);
                int kr = kk + (lane & 3);
                uint32_t b0 = __float_as_uint(Ws[kr][cb]);
                uint32_t b1 = __float_as_uint(Ws[kr + 4][cb]);
                mma_tf32(acc[0][nt], afr[0], b0, b1);
                mma_tf32(acc[1][nt], afr[1], b0, b1);
            }
        }
    }

    // ---- epilogue: fp32 g_h ----
#pragma unroll
    for (int mt = 0; mt < 2; mt++) {
        int rA = i0 + warp_m * 32 + mt * 16 + (lane >> 2);
#pragma unroll
        for (int nt = 0; nt < 2; nt++) {
            int c = c0 + warp_n * 16 + nt * 8 + 2 * (lane & 3);
            *(float2*)&g_h[(size_t)rA * D_OUT + c] =
                make_float2(acc[mt][nt][0], acc[mt][nt][1]);
            *(float2*)&g_h[(size_t)(rA + 8) * D_OUT + c] =
                make_float2(acc[mt][nt][2], acc[mt][nt][3]);
        }
    }

    // ---- transposed fp16 via smem bounce ----
    __syncthreads();
    float (*Tr)[65] = (float(*)[65])pool;    // 64x65 = 4160 <= 4608
#pragma unroll
    for (int mt = 0; mt < 2; mt++) {
        int rl = warp_m * 32 + mt * 16 + (lane >> 2);
#pragma unroll
        for (int nt = 0; nt < 2; nt++) {
            int cl = warp_n * 16 + nt * 8 + 2 * (lane & 3);
            Tr[cl][rl]         = acc[mt][nt][0];
            Tr[cl + 1][rl]     = acc[mt][nt][1];
            Tr[cl][rl + 8]     = acc[mt][nt][2];
            Tr[cl + 1][rl + 8] = acc[mt][nt][3];
        }
    }
    __syncthreads();
    {
        int c = tid >> 2, q = tid & 3;
        __half hbuf[16];
#pragma unroll
        for (int v = 0; v < 16; v++)
            hbuf[v] = __float2half_rn(Tr[c][q * 16 + v]);
        __half* dst = &g_htT[(size_t)(c0 + c) * N_NODES + i0 + q * 16];
        *(uint4*)&dst[0] = *(const uint4*)&hbuf[0];
        *(uint4*)&dst[8] = *(const uint4*)&hbuf[8];
    }
}

// ---------------------------------------------------------------------------
// Kernel A2: mu/xi dots + precomputed exp tables.
// ---------------------------------------------------------------------------
__global__ __launch_bounds__(256) void mu_xi_kernel(const float* __restrict__ wm,
                                                    const float* __restrict__ wx) {
    int warp = (blockIdx.x * blockDim.x + threadIdx.x) >> 5;
    int lane = threadIdx.x & 31;
    if (warp >= N_NODES) return;
    const float* hr = &g_h[warp * D_OUT];
    float mu = 0.f, xi = 0.f;
#pragma unroll
    for (int c = lane; c < D_OUT; c += 32) {
        float v = hr[c];
        mu += v * __ldg(&wm[c]);
        xi += v * __ldg(&wx[c]);
    }
#pragma unroll
    for (int o = 16; o; o >>= 1) {
        mu += __shfl_xor_sync(0xFFFFFFFFu, mu, o);
        xi += __shfl_xor_sync(0xFFFFFFFFu, xi, o);
    }
    if (lane == 0) {
        g_emu[warp] = __expf(mu);
        g_fmu[warp] = __expf(ALPHA * mu);
        g_exf[2 * warp]     = __expf(xi);
        g_exf[2 * warp + 1] = __expf(ALPHA * xi);
    }
}

// ---------------------------------------------------------------------------
// Kernel B: fused masked softmax + aggregation, fp16 m16n8k16 mma + ldmatrix.
// p_ij = adj ? (Emu_i*Exi_j >= 1 ? Emu_i*Exi_j : Fmu_i*Fxi_j) : 0   (fp16-rnd)
// CTA: 64 rows x 256 cols, 512 threads, 16 warps (2x8), warp tile 32x32.
// Fragments via ldmatrix.x4 (80B strides are LDSM bank-conflict-free).
// ---------------------------------------------------------------------------
#define BM 64
#define KT 32
#define NJT (N_NODES / KT)
#define PT_STRIDE 80
#define PT_BYTES  (BM * PT_STRIDE)          // 5120
#define HS_STRIDE 80
#define HS_BYTES  (D_OUT * HS_STRIDE)       // 20480
#define PT_OFF    0
#define HS_OFF    (2 * PT_BYTES)            // 10240
#define ZB_OFF    (HS_OFF + 2 * HS_BYTES)   // 51200
#define ZS_OFF    (ZB_OFF + BM * 8 * 4)     // 53248
#define SM_BYTES  (ZS_OFF + BM * 4)         // 53504

__global__ __launch_bounds__(512, 1) void attn_agg(const int* __restrict__ adj,
                                                   float* __restrict__ out) {
    extern __shared__ char sm[];
    const uint32_t base = smem_u32(sm);
    float* zbuf = (float*)(sm + ZB_OFF);
    float* Zs   = (float*)(sm + ZS_OFF);

    const int tid  = threadIdx.x;
    const int lane = tid & 31;
    const int warp = tid >> 5;
    const int warp_m = warp >> 3;           // 0..1
    const int warp_n = warp & 7;            // 0..7
    const int i0 = blockIdx.x * BM;

    // producer role: row pr (0..63), 4 j's at pjc = (tid&7)*4
    const int pr  = tid >> 3;
    const int pjc = (tid & 7) * 4;
    const float emu_r = g_emu[i0 + pr];
    const float fmu_r = g_fmu[i0 + pr];
    const int4* __restrict__ arow =
        (const int4*)(adj + (size_t)(i0 + pr) * N_NODES);

    float acc[2][4][4];
#pragma unroll
    for (int m = 0; m < 2; m++)
#pragma unroll
        for (int n = 0; n < 4; n++)
#pragma unroll
            for (int q = 0; q < 4; q++) acc[m][n][q] = 0.f;
    float zpart = 0.f;

    auto write_P = [&](int buf, int4 am4, float4 e0, float4 e1) {
        int am[4] = {am4.x, am4.y, am4.z, am4.w};
        float es[8] = {e0.x, e0.y, e0.z, e0.w, e1.x, e1.y, e1.z, e1.w};
        __half hp[4];
        float z = 0.f;
#pragma unroll
        for (int q = 0; q < 4; q++) {
            float ge = emu_r * es[2 * q];
            float fe = fmu_r * es[2 * q + 1];
            float v = (ge >= 1.f) ? ge : fe;
            __half hv = (am[q] > 0) ? __float2half_rn(v) : __half(0.f);
            hp[q] = hv;
            z += __half2float(hv);
        }
        char* dst = sm + PT_OFF + buf * PT_BYTES + pr * PT_STRIDE + pjc * 2;
        *(uint2*)dst = *(const uint2*)hp;
        return z;
    };

    auto issue_H = [&](int buf, int j0) {
#pragma unroll
        for (int t = 0; t < 2; t++) {
            int lin = tid + t * 512;        // 0..1023
            int c = lin >> 2, q = lin & 3;
            uint32_t dst = base + HS_OFF + buf * HS_BYTES +
                           (uint32_t)(c * HS_STRIDE + q * 16);
            CP_ASYNC16(dst, &g_htT[(size_t)c * N_NODES + j0 + q * 8]);
        }
    };

    // ---- Prologue: tile 0 -> buf 0; prefetch tile-1 regs ----
    int4   aA = arow[pjc >> 2];
    float4 ef0 = *(const float4*)&g_exf[2 * pjc];
    float4 ef1 = *(const float4*)&g_exf[2 * pjc + 4];
    issue_H(0, 0);
    zpart += write_P(0, aA, ef0, ef1);
    aA  = arow[(KT + pjc) >> 2];
    ef0 = *(const float4*)&g_exf[2 * (KT + pjc)];
    ef1 = *(const float4*)&g_exf[2 * (KT + pjc) + 4];
    CP_ASYNC_WAIT_ALL();
    __syncthreads();

    for (int jt = 0; jt < NJT; jt++) {
        const int buf = jt & 1;
        const int nbuf = buf ^ 1;

        // ---- produce tile jt+1 into nbuf ----
        if (jt + 1 < NJT) {
            issue_H(nbuf, (jt + 1) * KT);
            zpart += write_P(nbuf, aA, ef0, ef1);
            if (jt + 2 < NJT) {
                int j2 = (jt + 2) * KT;
                aA  = arow[(j2 + pjc) >> 2];
                ef0 = *(const float4*)&g_exf[2 * (j2 + pjc)];
                ef1 = *(const float4*)&g_exf[2 * (j2 + pjc) + 4];
            }
        }

        // ---- MMA on buf: 2 k-steps of 16, fragments via ldmatrix.x4 ----
        {
            const uint32_t ptb = base + PT_OFF + buf * PT_BYTES;
            const uint32_t hsb = base + HS_OFF + buf * HS_BYTES;
#pragma unroll
            for (int ks = 0; ks < 2; ks++) {
                uint32_t afr[2][4];
#pragma unroll
                for (int mt = 0; mt < 2; mt++) {
                    int r0 = warp_m * 32 + mt * 16;
                    uint32_t addr = ptb +
                        (uint32_t)((r0 + (lane & 15)) * PT_STRIDE +
                                   ks * 32 + (lane >> 4) * 16);
                    LDSM_X4(afr[mt], addr);
                }
                uint32_t bfr[2][4];
#pragma unroll
                for (int ntp = 0; ntp < 2; ntp++) {
                    int c0 = warp_n * 32 + ntp * 16;
                    uint32_t addr = hsb +
                        (uint32_t)((c0 + (lane & 7) + ((lane >> 4) << 3)) * HS_STRIDE +
                                   ks * 32 + ((lane >> 3) & 1) * 16);
                    LDSM_X4(bfr[ntp], addr);
                }
#pragma unroll
                for (int nt = 0; nt < 4; nt++) {
                    uint32_t b0 = bfr[nt >> 1][(nt & 1) * 2];
                    uint32_t b1 = bfr[nt >> 1][(nt & 1) * 2 + 1];
                    mma_f16(acc[0][nt], afr[0], b0, b1);
                    mma_f16(acc[1][nt], afr[1], b0, b1);
                }
            }
        }

        if (jt + 1 < NJT) CP_ASYNC_WAIT_ALL();
        __syncthreads();
    }

    // ---- Z reduction ----
    zbuf[pr * 8 + (tid & 7)] = zpart;
    __syncthreads();
    if (tid < BM) {
        float s = 0.f;
#pragma unroll
        for (int t = 0; t < 8; t++) s += zbuf[tid * 8 + t];
        Zs[tid] = s;
    }
    __syncthreads();

    // ---- Epilogue: normalize + ELU ----
#pragma unroll
    for (int mt = 0; mt < 2; mt++) {
        int rA = warp_m * 32 + mt * 16 + (lane >> 2);
        int rB = rA + 8;
        float izA = 1.f / Zs[rA];
        float izB = 1.f / Zs[rB];
#pragma unroll
        for (int nt = 0; nt < 4; nt++) {
            int c = warp_n * 32 + nt * 8 + 2 * (lane & 3);
            float v0 = acc[mt][nt][0] * izA;
            float v1 = acc[mt][nt][1] * izA;
            float v2 = acc[mt][nt][2] * izB;
            float v3 = acc[mt][nt][3] * izB;
            float2 oA, oB;
            oA.x = (v0 > 0.f) ? v0 : (__expf(v0) - 1.f);
            oA.y = (v1 > 0.f) ? v1 : (__expf(v1) - 1.f);
            oB.x = (v2 > 0.f) ? v2 : (__expf(v2) - 1.f);
            oB.y = (v3 > 0.f) ? v3 : (__expf(v3) - 1.f);
            *(float2*)&out[(size_t)(i0 + rA) * D_OUT + c] = oA;
            *(float2*)&out[(size_t)(i0 + rB) * D_OUT + c] = oB;
        }
    }
}

// ---------------------------------------------------------------------------
extern "C" void kernel_launch(void* const* d_in, const int* in_sizes, int n_in,
                              void* d_out, int out_size) {
    const float* features = (const float*)d_in[0];
    const int*   adj      = (const int*)d_in[1];
    const float* W_phi    = (const float*)d_in[2];
    const float* w_mu     = (const float*)d_in[3];
    const float* w_xi     = (const float*)d_in[4];
    float* out = (float*)d_out;

    (void)in_sizes; (void)n_in; (void)out_size;

    dim3 gA(N_NODES / 64, D_OUT / 64);
    gemm_xw<<<gA, 256>>>(features, W_phi);

    mu_xi_kernel<<<(N_NODES * 32) / 256, 256>>>(w_mu, w_xi);

    cudaFuncSetAttribute(attn_agg, cudaFuncAttributeMaxDynamicSharedMemorySize,
                         SM_BYTES);
    attn_agg<<<N_NODES / BM, 512, SM_BYTES>>>(adj, out);
}

// round 14
// speedup vs baseline: 3.5126x; 1.0719x over previous
#include <cuda_runtime.h>
#include <cuda_fp16.h>
#include <cstdint>

#define N_NODES 8192
#define D_IN    512
#define D_OUT   256
#define ALPHA   0.2f

// Scratch (allocation-free rule: __device__ globals)
__device__ float  g_h  [N_NODES * D_OUT];   // fp32 h (for mu/xi)
__device__ __half g_htT[D_OUT * N_NODES];   // transposed fp16 h: [c][j] (B operand)
__device__ float  g_emu[N_NODES];           // exp(mu_i)
__device__ float  g_fmu[N_NODES];           // exp(ALPHA*mu_i)
__device__ float  g_exf[2 * N_NODES];       // interleaved (exp(xi_j), exp(ALPHA*xi_j))
__device__ float  g_num[N_NODES * D_OUT];   // attn numerator accumulator
__device__ float  g_Z  [N_NODES];           // attn denominator accumulator

__device__ __forceinline__ float to_tf32(float x) {
    uint32_t u;
    asm("cvt.rna.tf32.f32 %0, %1;" : "=r"(u) : "f"(x));
    return __uint_as_float(u);
}

__device__ __forceinline__ uint32_t smem_u32(const void* p) {
    uint32_t a;
    asm("{ .reg .u64 t; cvta.to.shared.u64 t, %1; cvt.u32.u64 %0, t; }"
        : "=r"(a) : "l"(p));
    return a;
}

__device__ __forceinline__ void mma_f16(float c[4], const uint32_t a[4],
                                        uint32_t b0, uint32_t b1) {
    asm volatile(
        "mma.sync.aligned.m16n8k16.row.col.f32.f16.f16.f32 "
        "{%0,%1,%2,%3}, {%4,%5,%6,%7}, {%8,%9}, {%0,%1,%2,%3};"
        : "+f"(c[0]), "+f"(c[1]), "+f"(c[2]), "+f"(c[3])
        : "r"(a[0]), "r"(a[1]), "r"(a[2]), "r"(a[3]), "r"(b0), "r"(b1));
}

__device__ __forceinline__ void mma_tf32(float c[4], const uint32_t a[4],
                                         uint32_t b0, uint32_t b1) {
    asm volatile(
        "mma.sync.aligned.m16n8k8.row.col.f32.tf32.tf32.f32 "
        "{%0,%1,%2,%3}, {%4,%5,%6,%7}, {%8,%9}, {%0,%1,%2,%3};"
        : "+f"(c[0]), "+f"(c[1]), "+f"(c[2]), "+f"(c[3])
        : "r"(a[0]), "r"(a[1]), "r"(a[2]), "r"(a[3]), "r"(b0), "r"(b1));
}

#define LDSM_X4(r, addr) \
    asm volatile("ldmatrix.sync.aligned.m8n8.x4.shared.b16 {%0,%1,%2,%3}, [%4];" \
                 : "=r"((r)[0]), "=r"((r)[1]), "=r"((r)[2]), "=r"((r)[3]) \
                 : "r"(addr))

#define CP_ASYNC16(dst, src) \
    asm volatile("cp.async.cg.shared.global [%0], [%1], 16;" :: "r"(dst), "l"(src) : "memory")
#define CP_ASYNC_WAIT_ALL() \
    asm volatile("cp.async.wait_all;" ::: "memory")

// ---------------------------------------------------------------------------
// Kernel A: h = X @ W via tf32 mma.sync, double-buffered smem + LDG pipeline.
// CTA 64x64, 8 warps (2x4), warp tile 32x16.
// Epilogue: fp32 g_h + transposed fp16 g_htT (smem bounce, coalesced).
// ---------------------------------------------------------------------------
__global__ __launch_bounds__(256) void gemm_xw(const float* __restrict__ X,
                                               const float* __restrict__ W) {
    __shared__ float Xs[2][64][36];
    __shared__ float Ws[2][32][72];
    const int tid  = threadIdx.x;
    const int lane = tid & 31;
    const int wid  = tid >> 5;
    const int warp_m = wid >> 2;
    const int warp_n = wid & 3;
    const int i0 = blockIdx.x * 64;
    const int c0 = blockIdx.y * 64;

    const int xr0 = tid >> 3,         xq0 = tid & 7;
    const int xr1 = (tid + 256) >> 3, xq1 = (tid + 256) & 7;
    const int wr0 = tid >> 4,         wq0 = tid & 15;
    const int wr1 = (tid + 256) >> 4, wq1 = (tid + 256) & 15;

    float4 rx0, rx1, rw0, rw1;
    auto ldg_tile = [&](int k0) {
        rx0 = *(const float4*)&X[(size_t)(i0 + xr0) * D_IN + k0 + xq0 * 4];
        rx1 = *(const float4*)&X[(size_t)(i0 + xr1) * D_IN + k0 + xq1 * 4];
        rw0 = *(const float4*)&W[(size_t)(k0 + wr0) * D_OUT + c0 + wq0 * 4];
        rw1 = *(const float4*)&W[(size_t)(k0 + wr1) * D_OUT + c0 + wq1 * 4];
    };
    auto sts_tile = [&](int b) {
        float4 v;
        v = rx0; v.x = to_tf32(v.x); v.y = to_tf32(v.y); v.z = to_tf32(v.z); v.w = to_tf32(v.w);
        *(float4*)&Xs[b][xr0][xq0 * 4] = v;
        v = rx1; v.x = to_tf32(v.x); v.y = to_tf32(v.y); v.z = to_tf32(v.z); v.w = to_tf32(v.w);
        *(float4*)&Xs[b][xr1][xq1 * 4] = v;
        v = rw0; v.x = to_tf32(v.x); v.y = to_tf32(v.y); v.z = to_tf32(v.z); v.w = to_tf32(v.w);
        *(float4*)&Ws[b][wr0][wq0 * 4] = v;
        v = rw1; v.x = to_tf32(v.x); v.y = to_tf32(v.y); v.z = to_tf32(v.z); v.w = to_tf32(v.w);
        *(float4*)&Ws[b][wr1][wq1 * 4] = v;
    };

    float acc[2][2][4];
#pragma unroll
    for (int m = 0; m < 2; m++)
#pragma unroll
        for (int n = 0; n < 2; n++)
#pragma unroll
            for (int q = 0; q < 4; q++) acc[m][n][q] = 0.f;

    ldg_tile(0);
    sts_tile(0);
    ldg_tile(32);
    __syncthreads();

#pragma unroll 4
    for (int it = 0; it < 16; it++) {
        const int b = it & 1;
        if (it + 1 < 16) sts_tile(b ^ 1);
        if (it + 2 < 16) ldg_tile((it + 2) * 32);
#pragma unroll
        for (int ks = 0; ks < 4; ks++) {
            const int kk = ks * 8;
            uint32_t afr[2][4];
#pragma unroll
            for (int mt = 0; mt < 2; mt++) {
                int r0 = warp_m * 32 + mt * 16 + (lane >> 2);
                int kc = kk + (lane & 3);
                afr[mt][0] = __float_as_uint(Xs[b][r0][kc]);
                afr[mt][1] = __float_as_uint(Xs[b][r0 + 8][kc]);
                afr[mt][2] = __float_as_uint(Xs[b][r0][kc + 4]);
                afr[mt][3] = __float_as_uint(Xs[b][r0 + 8][kc + 4]);
            }
#pragma unroll
            for (int nt = 0; nt < 2; nt++) {
                int cb = warp_n * 16 + nt * 8 + (lane >> 2);
                int kr = kk + (lane & 3);
                uint32_t b0 = __float_as_uint(Ws[b][kr][cb]);
                uint32_t b1 = __float_as_uint(Ws[b][kr + 4][cb]);
                mma_tf32(acc[0][nt], afr[0], b0, b1);
                mma_tf32(acc[1][nt], afr[1], b0, b1);
            }
        }
        __syncthreads();
    }

    // ---- epilogue: fp32 g_h ----
#pragma unroll
    for (int mt = 0; mt < 2; mt++) {
        int rA = i0 + warp_m * 32 + mt * 16 + (lane >> 2);
#pragma unroll
        for (int nt = 0; nt < 2; nt++) {
            int c = c0 + warp_n * 16 + nt * 8 + 2 * (lane & 3);
            *(float2*)&g_h[(size_t)rA * D_OUT + c] =
                make_float2(acc[mt][nt][0], acc[mt][nt][1]);
            *(float2*)&g_h[(size_t)(rA + 8) * D_OUT + c] =
                make_float2(acc[mt][nt][2], acc[mt][nt][3]);
        }
    }

    // ---- transposed fp16 via smem bounce (reuse Xs; prior loop ended in sync) ----
    float (*Tr)[65] = (float(*)[65]) & Xs[0][0][0];   // 64*65*4 <= 18432
#pragma unroll
    for (int mt = 0; mt < 2; mt++) {
        int rl = warp_m * 32 + mt * 16 + (lane >> 2);
#pragma unroll
        for (int nt = 0; nt < 2; nt++) {
            int cl = warp_n * 16 + nt * 8 + 2 * (lane & 3);
            Tr[cl][rl]         = acc[mt][nt][0];
            Tr[cl + 1][rl]     = acc[mt][nt][1];
            Tr[cl][rl + 8]     = acc[mt][nt][2];
            Tr[cl + 1][rl + 8] = acc[mt][nt][3];
        }
    }
    __syncthreads();
    {
        int c = tid >> 2, q = tid & 3;
        __half hbuf[16];
#pragma unroll
        for (int v = 0; v < 16; v++)
            hbuf[v] = __float2half_rn(Tr[c][q * 16 + v]);
        __half* dst = &g_htT[(size_t)(c0 + c) * N_NODES + i0 + q * 16];
        *(uint4*)&dst[0] = *(const uint4*)&hbuf[0];
        *(uint4*)&dst[8] = *(const uint4*)&hbuf[8];
    }
}

// ---------------------------------------------------------------------------
// Kernel A2: mu/xi dots + precomputed exp tables.
// ---------------------------------------------------------------------------
__global__ __launch_bounds__(256) void mu_xi_kernel(const float* __restrict__ wm,
                                                    const float* __restrict__ wx) {
    int warp = (blockIdx.x * blockDim.x + threadIdx.x) >> 5;
    int lane = threadIdx.x & 31;
    if (warp >= N_NODES) return;
    const float* hr = &g_h[warp * D_OUT];
    float mu = 0.f, xi = 0.f;
#pragma unroll
    for (int c = lane; c < D_OUT; c += 32) {
        float v = hr[c];
        mu += v * __ldg(&wm[c]);
        xi += v * __ldg(&wx[c]);
    }
#pragma unroll
    for (int o = 16; o; o >>= 1) {
        mu += __shfl_xor_sync(0xFFFFFFFFu, mu, o);
        xi += __shfl_xor_sync(0xFFFFFFFFu, xi, o);
    }
    if (lane == 0) {
        g_emu[warp] = __expf(mu);
        g_fmu[warp] = __expf(ALPHA * mu);
        g_exf[2 * warp]     = __expf(xi);
        g_exf[2 * warp + 1] = __expf(ALPHA * xi);
    }
}

// ---------------------------------------------------------------------------
// Zero accumulators.
// ---------------------------------------------------------------------------
__global__ __launch_bounds__(512) void zero_kernel() {
    int idx = blockIdx.x * 512 + threadIdx.x;       // 524288 float4
    ((float4*)g_num)[idx] = make_float4(0.f, 0.f, 0.f, 0.f);
    if (idx < N_NODES / 4)
        ((float4*)g_Z)[idx] = make_float4(0.f, 0.f, 0.f, 0.f);
}

// ---------------------------------------------------------------------------
// Kernel B: attention aggregation, grid = 1024 plain CTAs.
// CTA (iblk, jc) = (bid>>3, bid&7): rows [iblk*64, +64), j-tiles
// [jc*32, +32). Identical double-buffered tile loop as R11; partials
// flushed with atomicAdd into g_num / g_Z. HW scheduler balances the
// 1024 units over 148 SMs (~7 unit-times vs 8 at 128 CTAs).
// ---------------------------------------------------------------------------
#define BM 64
#define KT 32
#define UT_TILES 32
#define PT_STRIDE 80
#define PT_BYTES  (BM * PT_STRIDE)          // 5120
#define HS_STRIDE 80
#define HS_BYTES  (D_OUT * HS_STRIDE)       // 20480
#define PT_OFF    0
#define HS_OFF    (2 * PT_BYTES)            // 10240
#define SM_BYTES  (HS_OFF + 2 * HS_BYTES)   // 51200

__global__ __launch_bounds__(512, 1) void attn_agg(const int* __restrict__ adj) {
    extern __shared__ char sm[];
    const uint32_t base = smem_u32(sm);

    const int tid  = threadIdx.x;
    const int lane = tid & 31;
    const int warp = tid >> 5;
    const int warp_m = warp >> 3;           // 0..1
    const int warp_n = warp & 7;            // 0..7

    const int iblk = blockIdx.x >> 3;       // 0..127
    const int jc   = blockIdx.x & 7;        // 0..7
    const int i0   = iblk * BM;
    const int ut0  = jc * UT_TILES;         // first j-tile

    const int pr  = tid >> 3;               // 0..63 (row in block)
    const int pjc = (tid & 7) * 4;          // j sub-chunk
    const float emu_r = g_emu[i0 + pr];
    const float fmu_r = g_fmu[i0 + pr];
    const int4* __restrict__ arow =
        (const int4*)(adj + (size_t)(i0 + pr) * N_NODES);

    float acc[2][4][4];
#pragma unroll
    for (int m = 0; m < 2; m++)
#pragma unroll
        for (int n = 0; n < 4; n++)
#pragma unroll
            for (int q = 0; q < 4; q++) acc[m][n][q] = 0.f;
    float zpart = 0.f;

    auto write_P = [&](int buf, int4 am4, float4 e0, float4 e1) {
        int am[4] = {am4.x, am4.y, am4.z, am4.w};
        float es[8] = {e0.x, e0.y, e0.z, e0.w, e1.x, e1.y, e1.z, e1.w};
        __half hp[4];
        float z = 0.f;
#pragma unroll
        for (int q = 0; q < 4; q++) {
            float ge = emu_r * es[2 * q];
            float fe = fmu_r * es[2 * q + 1];
            float v = (ge >= 1.f) ? ge : fe;
            __half hv = (am[q] > 0) ? __float2half_rn(v) : __half(0.f);
            hp[q] = hv;
            z += __half2float(hv);
        }
        char* dst = sm + PT_OFF + buf * PT_BYTES + pr * PT_STRIDE + pjc * 2;
        *(uint2*)dst = *(const uint2*)hp;
        return z;
    };

    auto issue_H = [&](int buf, int j0) {
#pragma unroll
        for (int t = 0; t < 2; t++) {
            int lin = tid + t * 512;
            int c = lin >> 2, q = lin & 3;
            uint32_t dst = base + HS_OFF + buf * HS_BYTES +
                           (uint32_t)(c * HS_STRIDE + q * 16);
            CP_ASYNC16(dst, &g_htT[(size_t)c * N_NODES + j0 + q * 8]);
        }
    };

    // ---- prologue: tile ut0 -> buf 0; prefetch ut0+1 regs ----
    const int j0 = ut0 * KT;
    int4   aA = arow[(j0 + pjc) >> 2];
    float4 ef0 = *(const float4*)&g_exf[2 * (j0 + pjc)];
    float4 ef1 = *(const float4*)&g_exf[2 * (j0 + pjc) + 4];
    issue_H(0, j0);
    zpart += write_P(0, aA, ef0, ef1);
    aA  = arow[(j0 + KT + pjc) >> 2];
    ef0 = *(const float4*)&g_exf[2 * (j0 + KT + pjc)];
    ef1 = *(const float4*)&g_exf[2 * (j0 + KT + pjc) + 4];
    CP_ASYNC_WAIT_ALL();
    __syncthreads();

    for (int t = 0; t < UT_TILES; t++) {
        const int buf = t & 1;
        const int nbuf = buf ^ 1;

        if (t + 1 < UT_TILES) {
            issue_H(nbuf, (ut0 + t + 1) * KT);
            zpart += write_P(nbuf, aA, ef0, ef1);
            if (t + 2 < UT_TILES) {
                int j2 = (ut0 + t + 2) * KT;
                aA  = arow[(j2 + pjc) >> 2];
                ef0 = *(const float4*)&g_exf[2 * (j2 + pjc)];
                ef1 = *(const float4*)&g_exf[2 * (j2 + pjc) + 4];
            }
        }

        // ---- MMA on buf ----
        {
            const uint32_t ptb = base + PT_OFF + buf * PT_BYTES;
            const uint32_t hsb = base + HS_OFF + buf * HS_BYTES;
#pragma unroll
            for (int ks = 0; ks < 2; ks++) {
                uint32_t afr[2][4];
#pragma unroll
                for (int mt = 0; mt < 2; mt++) {
                    int r0 = warp_m * 32 + mt * 16;
                    uint32_t addr = ptb +
                        (uint32_t)((r0 + (lane & 15)) * PT_STRIDE +
                                   ks * 32 + (lane >> 4) * 16);
                    LDSM_X4(afr[mt], addr);
                }
                uint32_t bfr[2][4];
#pragma unroll
                for (int ntp = 0; ntp < 2; ntp++) {
                    int c0 = warp_n * 32 + ntp * 16;
                    uint32_t addr = hsb +
                        (uint32_t)((c0 + (lane & 7) + ((lane >> 4) << 3)) * HS_STRIDE +
                                   ks * 32 + ((lane >> 3) & 1) * 16);
                    LDSM_X4(bfr[ntp], addr);
                }
#pragma unroll
                for (int nt = 0; nt < 4; nt++) {
                    uint32_t b0 = bfr[nt >> 1][(nt & 1) * 2];
                    uint32_t b1 = bfr[nt >> 1][(nt & 1) * 2 + 1];
                    mma_f16(acc[0][nt], afr[0], b0, b1);
                    mma_f16(acc[1][nt], afr[1], b0, b1);
                }
            }
        }

        if (t + 1 < UT_TILES) CP_ASYNC_WAIT_ALL();
        __syncthreads();
    }

    // ---- Z partial reduce (reuse dead P buffer) + atomic flush ----
    float* zbuf = (float*)(sm + PT_OFF);    // 64*8 floats = 2KB < PT_BYTES
    zbuf[pr * 8 + (tid & 7)] = zpart;
    __syncthreads();
    if (tid < BM) {
        float s = 0.f;
#pragma unroll
        for (int t = 0; t < 8; t++) s += zbuf[tid * 8 + t];
        atomicAdd(&g_Z[i0 + tid], s);
    }

    // ---- numerator atomic flush ----
#pragma unroll
    for (int mt = 0; mt < 2; mt++) {
        int rA = i0 + warp_m * 32 + mt * 16 + (lane >> 2);
#pragma unroll
        for (int nt = 0; nt < 4; nt++) {
            int c = warp_n * 32 + nt * 8 + 2 * (lane & 3);
            atomicAdd(&g_num[(size_t)rA * D_OUT + c],           acc[mt][nt][0]);
            atomicAdd(&g_num[(size_t)rA * D_OUT + c + 1],       acc[mt][nt][1]);
            atomicAdd(&g_num[(size_t)(rA + 8) * D_OUT + c],     acc[mt][nt][2]);
            atomicAdd(&g_num[(size_t)(rA + 8) * D_OUT + c + 1], acc[mt][nt][3]);
        }
    }
}

// ---------------------------------------------------------------------------
// Finalize: out = elu(num / Z)
// ---------------------------------------------------------------------------
__global__ __launch_bounds__(512) void finalize(float* __restrict__ out) {
    int idx = blockIdx.x * 512 + threadIdx.x;       // 524288 float4
    int row = idx >> 6;                             // 64 float4 per row
    float iz = 1.f / g_Z[row];
    float4 v = ((const float4*)g_num)[idx];
    float a = v.x * iz, b = v.y * iz, c = v.z * iz, d = v.w * iz;
    float4 o;
    o.x = (a > 0.f) ? a : (__expf(a) - 1.f);
    o.y = (b > 0.f) ? b : (__expf(b) - 1.f);
    o.z = (c > 0.f) ? c : (__expf(c) - 1.f);
    o.w = (d > 0.f) ? d : (__expf(d) - 1.f);
    ((float4*)out)[idx] = o;
}

// ---------------------------------------------------------------------------
extern "C" void kernel_launch(void* const* d_in, const int* in_sizes, int n_in,
                              void* d_out, int out_size) {
    const float* features = (const float*)d_in[0];
    const int*   adj      = (const int*)d_in[1];
    const float* W_phi    = (const float*)d_in[2];
    const float* w_mu     = (const float*)d_in[3];
    const float* w_xi     = (const float*)d_in[4];
    float* out = (float*)d_out;

    (void)in_sizes; (void)n_in; (void)out_size;

    zero_kernel<<<(N_NODES * D_OUT / 4) / 512, 512>>>();

    dim3 gA(N_NODES / 64, D_OUT / 64);
    gemm_xw<<<gA, 256>>>(features, W_phi);

    mu_xi_kernel<<<(N_NODES * 32) / 256, 256>>>(w_mu, w_xi);

    cudaFuncSetAttribute(attn_agg, cudaFuncAttributeMaxDynamicSharedMemorySize,
                         SM_BYTES);
    attn_agg<<<(N_NODES / BM) * 8, 512, SM_BYTES>>>(adj);

    finalize<<<(N_NODES * D_OUT / 4) / 512, 512>>>(out);
}

// round 17
// speedup vs baseline: 4.6429x; 1.3218x over previous
#include <cuda_runtime.h>
#include <cuda_fp16.h>
#include <cstdint>

#define N_NODES 8192
#define D_IN    512
#define D_OUT   256
#define ALPHA   0.2f

// Scratch (allocation-free rule: __device__ globals)
__device__ float  g_h  [N_NODES * D_OUT];   // fp32 h (for mu/xi)
__device__ __half g_htT[D_OUT * N_NODES];   // transposed fp16 h: [c][j] (B operand)
__device__ float  g_emu[N_NODES];           // exp(mu_i)
__device__ float  g_fmu[N_NODES];           // exp(ALPHA*mu_i)
__device__ float  g_exf[2 * N_NODES];       // interleaved (exp(xi_j), exp(ALPHA*xi_j))
__device__ float  g_num[N_NODES * D_OUT];   // attn numerator accumulator
__device__ float  g_Z  [N_NODES];           // attn denominator accumulator

__device__ __forceinline__ float to_tf32(float x) {
    uint32_t u;
    asm("cvt.rna.tf32.f32 %0, %1;" : "=r"(u) : "f"(x));
    return __uint_as_float(u);
}

__device__ __forceinline__ uint32_t smem_u32(const void* p) {
    uint32_t a;
    asm("{ .reg .u64 t; cvta.to.shared.u64 t, %1; cvt.u32.u64 %0, t; }"
        : "=r"(a) : "l"(p));
    return a;
}

__device__ __forceinline__ void mma_f16(float c[4], const uint32_t a[4],
                                        uint32_t b0, uint32_t b1) {
    asm volatile(
        "mma.sync.aligned.m16n8k16.row.col.f32.f16.f16.f32 "
        "{%0,%1,%2,%3}, {%4,%5,%6,%7}, {%8,%9}, {%0,%1,%2,%3};"
        : "+f"(c[0]), "+f"(c[1]), "+f"(c[2]), "+f"(c[3])
        : "r"(a[0]), "r"(a[1]), "r"(a[2]), "r"(a[3]), "r"(b0), "r"(b1));
}

__device__ __forceinline__ void mma_tf32(float c[4], const uint32_t a[4],
                                         uint32_t b0, uint32_t b1) {
    asm volatile(
        "mma.sync.aligned.m16n8k8.row.col.f32.tf32.tf32.f32 "
        "{%0,%1,%2,%3}, {%4,%5,%6,%7}, {%8,%9}, {%0,%1,%2,%3};"
        : "+f"(c[0]), "+f"(c[1]), "+f"(c[2]), "+f"(c[3])
        : "r"(a[0]), "r"(a[1]), "r"(a[2]), "r"(a[3]), "r"(b0), "r"(b1));
}

#define LDSM_X4(r, addr) \
    asm volatile("ldmatrix.sync.aligned.m8n8.x4.shared.b16 {%0,%1,%2,%3}, [%4];" \
                 : "=r"((r)[0]), "=r"((r)[1]), "=r"((r)[2]), "=r"((r)[3]) \
                 : "r"(addr))

#define CP_ASYNC16(dst, src) \
    asm volatile("cp.async.cg.shared.global [%0], [%1], 16;" :: "r"(dst), "l"(src) : "memory")
#define CP_ASYNC_WAIT_ALL() \
    asm volatile("cp.async.wait_all;" ::: "memory")

// ---------------------------------------------------------------------------
// Kernel A: h = X @ W via tf32 mma.sync, double-buffered smem + LDG pipeline.
// CTA 64x64, 8 warps (2x4), warp tile 32x16.
// Epilogue: fp32 g_h + transposed fp16 g_htT (smem bounce, coalesced).
// ---------------------------------------------------------------------------
__global__ __launch_bounds__(256) void gemm_xw(const float* __restrict__ X,
                                               const float* __restrict__ W) {
    __shared__ float Xs[2][64][36];
    __shared__ float Ws[2][32][72];
    const int tid  = threadIdx.x;
    const int lane = tid & 31;
    const int wid  = tid >> 5;
    const int warp_m = wid >> 2;
    const int warp_n = wid & 3;
    const int i0 = blockIdx.x * 64;
    const int c0 = blockIdx.y * 64;

    const int xr0 = tid >> 3,         xq0 = tid & 7;
    const int xr1 = (tid + 256) >> 3, xq1 = (tid + 256) & 7;
    const int wr0 = tid >> 4,         wq0 = tid & 15;
    const int wr1 = (tid + 256) >> 4, wq1 = (tid + 256) & 15;

    float4 rx0, rx1, rw0, rw1;
    auto ldg_tile = [&](int k0) {
        rx0 = *(const float4*)&X[(size_t)(i0 + xr0) * D_IN + k0 + xq0 * 4];
        rx1 = *(const float4*)&X[(size_t)(i0 + xr1) * D_IN + k0 + xq1 * 4];
        rw0 = *(const float4*)&W[(size_t)(k0 + wr0) * D_OUT + c0 + wq0 * 4];
        rw1 = *(const float4*)&W[(size_t)(k0 + wr1) * D_OUT + c0 + wq1 * 4];
    };
    auto sts_tile = [&](int b) {
        float4 v;
        v = rx0; v.x = to_tf32(v.x); v.y = to_tf32(v.y); v.z = to_tf32(v.z); v.w = to_tf32(v.w);
        *(float4*)&Xs[b][xr0][xq0 * 4] = v;
        v = rx1; v.x = to_tf32(v.x); v.y = to_tf32(v.y); v.z = to_tf32(v.z); v.w = to_tf32(v.w);
        *(float4*)&Xs[b][xr1][xq1 * 4] = v;
        v = rw0; v.x = to_tf32(v.x); v.y = to_tf32(v.y); v.z = to_tf32(v.z); v.w = to_tf32(v.w);
        *(float4*)&Ws[b][wr0][wq0 * 4] = v;
        v = rw1; v.x = to_tf32(v.x); v.y = to_tf32(v.y); v.z = to_tf32(v.z); v.w = to_tf32(v.w);
        *(float4*)&Ws[b][wr1][wq1 * 4] = v;
    };

    float acc[2][2][4];
#pragma unroll
    for (int m = 0; m < 2; m++)
#pragma unroll
        for (int n = 0; n < 2; n++)
#pragma unroll
            for (int q = 0; q < 4; q++) acc[m][n][q] = 0.f;

    ldg_tile(0);
    sts_tile(0);
    ldg_tile(32);
    __syncthreads();

#pragma unroll 4
    for (int it = 0; it < 16; it++) {
        const int b = it & 1;
        if (it + 1 < 16) sts_tile(b ^ 1);
        if (it + 2 < 16) ldg_tile((it + 2) * 32);
#pragma unroll
        for (int ks = 0; ks < 4; ks++) {
            const int kk = ks * 8;
            uint32_t afr[2][4];
#pragma unroll
            for (int mt = 0; mt < 2; mt++) {
                int r0 = warp_m * 32 + mt * 16 + (lane >> 2);
                int kc = kk + (lane & 3);
                afr[mt][0] = __float_as_uint(Xs[b][r0][kc]);
                afr[mt][1] = __float_as_uint(Xs[b][r0 + 8][kc]);
                afr[mt][2] = __float_as_uint(Xs[b][r0][kc + 4]);
                afr[mt][3] = __float_as_uint(Xs[b][r0 + 8][kc + 4]);
            }
#pragma unroll
            for (int nt = 0; nt < 2; nt++) {
                int cb = warp_n * 16 + nt * 8 + (lane >> 2);
                int kr = kk + (lane & 3);
                uint32_t b0 = __float_as_uint(Ws[b][kr][cb]);
                uint32_t b1 = __float_as_uint(Ws[b][kr + 4][cb]);
                mma_tf32(acc[0][nt], afr[0], b0, b1);
                mma_tf32(acc[1][nt], afr[1], b0, b1);
            }
        }
        __syncthreads();
    }

    // ---- epilogue: fp32 g_h ----
#pragma unroll
    for (int mt = 0; mt < 2; mt++) {
        int rA = i0 + warp_m * 32 + mt * 16 + (lane >> 2);
#pragma unroll
        for (int nt = 0; nt < 2; nt++) {
            int c = c0 + warp_n * 16 + nt * 8 + 2 * (lane & 3);
            *(float2*)&g_h[(size_t)rA * D_OUT + c] =
                make_float2(acc[mt][nt][0], acc[mt][nt][1]);
            *(float2*)&g_h[(size_t)(rA + 8) * D_OUT + c] =
                make_float2(acc[mt][nt][2], acc[mt][nt][3]);
        }
    }

    // ---- transposed fp16 via smem bounce (reuse Xs; prior loop ended in sync) ----
    float (*Tr)[65] = (float(*)[65]) & Xs[0][0][0];   // 64*65*4 <= 18432
#pragma unroll
    for (int mt = 0; mt < 2; mt++) {
        int rl = warp_m * 32 + mt * 16 + (lane >> 2);
#pragma unroll
        for (int nt = 0; nt < 2; nt++) {
            int cl = warp_n * 16 + nt * 8 + 2 * (lane & 3);
            Tr[cl][rl]         = acc[mt][nt][0];
            Tr[cl + 1][rl]     = acc[mt][nt][1];
            Tr[cl][rl + 8]     = acc[mt][nt][2];
            Tr[cl + 1][rl + 8] = acc[mt][nt][3];
        }
    }
    __syncthreads();
    {
        int c = tid >> 2, q = tid & 3;
        __half hbuf[16];
#pragma unroll
        for (int v = 0; v < 16; v++)
            hbuf[v] = __float2half_rn(Tr[c][q * 16 + v]);
        __half* dst = &g_htT[(size_t)(c0 + c) * N_NODES + i0 + q * 16];
        *(uint4*)&dst[0] = *(const uint4*)&hbuf[0];
        *(uint4*)&dst[8] = *(const uint4*)&hbuf[8];
    }
}

// ---------------------------------------------------------------------------
// Kernel A2: mu/xi dots + precomputed exp tables.
// ---------------------------------------------------------------------------
__global__ __launch_bounds__(256) void mu_xi_kernel(const float* __restrict__ wm,
                                                    const float* __restrict__ wx) {
    int warp = (blockIdx.x * blockDim.x + threadIdx.x) >> 5;
    int lane = threadIdx.x & 31;
    if (warp >= N_NODES) return;
    const float* hr = &g_h[warp * D_OUT];
    float mu = 0.f, xi = 0.f;
#pragma unroll
    for (int c = lane; c < D_OUT; c += 32) {
        float v = hr[c];
        mu += v * __ldg(&wm[c]);
        xi += v * __ldg(&wx[c]);
    }
#pragma unroll
    for (int o = 16; o; o >>= 1) {
        mu += __shfl_xor_sync(0xFFFFFFFFu, mu, o);
        xi += __shfl_xor_sync(0xFFFFFFFFu, xi, o);
    }
    if (lane == 0) {
        g_emu[warp] = __expf(mu);
        g_fmu[warp] = __expf(ALPHA * mu);
        g_exf[2 * warp]     = __expf(xi);
        g_exf[2 * warp + 1] = __expf(ALPHA * xi);
    }
}

// ---------------------------------------------------------------------------
// Zero accumulators.
// ---------------------------------------------------------------------------
__global__ __launch_bounds__(512) void zero_kernel() {
    int idx = blockIdx.x * 512 + threadIdx.x;       // 524288 float4
    ((float4*)g_num)[idx] = make_float4(0.f, 0.f, 0.f, 0.f);
    if (idx < N_NODES / 4)
        ((float4*)g_Z)[idx] = make_float4(0.f, 0.f, 0.f, 0.f);
}

// ---------------------------------------------------------------------------
// Kernel B: attention aggregation, grid = 1024 CTAs of 256 threads.
// CTA (iblk, jc) = (bid>>3, bid&7): rows [iblk*64,+64), j-tiles [jc*32,+32).
// 8 warps (2x4), warp tile 32x64 (2x8 m16n8k16 frags, 2x ILP vs R14).
// __launch_bounds__(256,2) -> 2 independent CTAs/SM: when one CTA stalls at
// its per-tile barrier/wait, the other's warps keep issuing (fixes the
// issue=20% lockstep found in R14 ncu). Partials flushed via atomicAdd.
// ---------------------------------------------------------------------------
#define BM 64
#define KT 32
#define UT_TILES 32
#define PT_STRIDE 80
#define PT_BYTES  (BM * PT_STRIDE)          // 5120
#define HS_STRIDE 80
#define HS_BYTES  (D_OUT * HS_STRIDE)       // 20480
#define PT_OFF    0
#define HS_OFF    (2 * PT_BYTES)            // 10240
#define SM_BYTES  (HS_OFF + 2 * HS_BYTES)   // 51200

__global__ __launch_bounds__(256, 2) void attn_agg(const int* __restrict__ adj) {
    extern __shared__ char sm[];
    const uint32_t base = smem_u32(sm);

    const int tid  = threadIdx.x;
    const int lane = tid & 31;
    const int warp = tid >> 5;
    const int warp_m = warp >> 2;           // 0..1
    const int warp_n = warp & 3;            // 0..3 (64-col groups)

    const int iblk = blockIdx.x >> 3;       // 0..127
    const int jc   = blockIdx.x & 7;        // 0..7
    const int i0   = iblk * BM;
    const int ut0  = jc * UT_TILES;         // first j-tile

    const int pr  = tid >> 2;               // 0..63 (row in block)
    const int pjc = (tid & 3) * 8;          // 8 j's per thread
    const float emu_r = g_emu[i0 + pr];
    const float fmu_r = g_fmu[i0 + pr];
    const int4* __restrict__ arow =
        (const int4*)(adj + (size_t)(i0 + pr) * N_NODES);

    float acc[2][8][4];
#pragma unroll
    for (int m = 0; m < 2; m++)
#pragma unroll
        for (int n = 0; n < 8; n++)
#pragma unroll
            for (int q = 0; q < 4; q++) acc[m][n][q] = 0.f;
    float zpart = 0.f;

    auto write_P = [&](int buf, int4 aA, int4 aB, const float4 ef[4]) {
        int am[8] = {aA.x, aA.y, aA.z, aA.w, aB.x, aB.y, aB.z, aB.w};
        __half hp[8];
        float z = 0.f;
#pragma unroll
        for (int q = 0; q < 4; q++) {
            float ge0 = emu_r * ef[q].x;
            float fe0 = fmu_r * ef[q].y;
            float ge1 = emu_r * ef[q].z;
            float fe1 = fmu_r * ef[q].w;
            float v0 = (ge0 >= 1.f) ? ge0 : fe0;
            float v1 = (ge1 >= 1.f) ? ge1 : fe1;
            __half h0 = (am[2 * q] > 0) ? __float2half_rn(v0) : __half(0.f);
            __half h1 = (am[2 * q + 1] > 0) ? __float2half_rn(v1) : __half(0.f);
            hp[2 * q] = h0; hp[2 * q + 1] = h1;
            z += __half2float(h0) + __half2float(h1);
        }
        char* dst = sm + PT_OFF + buf * PT_BYTES + pr * PT_STRIDE + pjc * 2;
        *(uint4*)dst = *(const uint4*)hp;
        return z;
    };

    auto issue_H = [&](int buf, int j0) {
#pragma unroll
        for (int t = 0; t < 4; t++) {
            int lin = tid + t * 256;        // 0..1023
            int c = lin >> 2, q = lin & 3;
            uint32_t dst = base + HS_OFF + buf * HS_BYTES +
                           (uint32_t)(c * HS_STRIDE + q * 16);
            CP_ASYNC16(dst, &g_htT[(size_t)c * N_NODES + j0 + q * 8]);
        }
    };

    // ---- prologue: tile ut0 -> buf 0; prefetch ut0+1 regs ----
    const int j0 = ut0 * KT;
    int4   aA = arow[(j0 + pjc) >> 2];
    int4   aB = arow[((j0 + pjc) >> 2) + 1];
    float4 ef[4];
#pragma unroll
    for (int q = 0; q < 4; q++)
        ef[q] = *(const float4*)&g_exf[2 * (j0 + pjc) + q * 4];
    issue_H(0, j0);
    zpart += write_P(0, aA, aB, ef);
    aA = arow[(j0 + KT + pjc) >> 2];
    aB = arow[((j0 + KT + pjc) >> 2) + 1];
#pragma unroll
    for (int q = 0; q < 4; q++)
        ef[q] = *(const float4*)&g_exf[2 * (j0 + KT + pjc) + q * 4];
    CP_ASYNC_WAIT_ALL();
    __syncthreads();

    for (int t = 0; t < UT_TILES; t++) {
        const int buf = t & 1;
        const int nbuf = buf ^ 1;

        if (t + 1 < UT_TILES) {
            issue_H(nbuf, (ut0 + t + 1) * KT);
            zpart += write_P(nbuf, aA, aB, ef);
            if (t + 2 < UT_TILES) {
                int j2 = (ut0 + t + 2) * KT;
                aA = arow[(j2 + pjc) >> 2];
                aB = arow[((j2 + pjc) >> 2) + 1];
#pragma unroll
                for (int q = 0; q < 4; q++)
                    ef[q] = *(const float4*)&g_exf[2 * (j2 + pjc) + q * 4];
            }
        }

        // ---- MMA on buf: warp tile 32x64, 2 k-steps, ldmatrix.x4 frags ----
        {
            const uint32_t ptb = base + PT_OFF + buf * PT_BYTES;
            const uint32_t hsb = base + HS_OFF + buf * HS_BYTES;
#pragma unroll
            for (int ks = 0; ks < 2; ks++) {
                uint32_t afr[2][4];
#pragma unroll
                for (int mt = 0; mt < 2; mt++) {
                    int r0 = warp_m * 32 + mt * 16;
                    uint32_t addr = ptb +
                        (uint32_t)((r0 + (lane & 15)) * PT_STRIDE +
                                   ks * 32 + (lane >> 4) * 16);
                    LDSM_X4(afr[mt], addr);
                }
                uint32_t bfr[4][4];
#pragma unroll
                for (int ntp = 0; ntp < 4; ntp++) {
                    int c0 = warp_n * 64 + ntp * 16;
                    uint32_t addr = hsb +
                        (uint32_t)((c0 + (lane & 7) + ((lane >> 4) << 3)) * HS_STRIDE +
                                   ks * 32 + ((lane >> 3) & 1) * 16);
                    LDSM_X4(bfr[ntp], addr);
                }
#pragma unroll
                for (int nt = 0; nt < 8; nt++) {
                    uint32_t b0 = bfr[nt >> 1][(nt & 1) * 2];
                    uint32_t b1 = bfr[nt >> 1][(nt & 1) * 2 + 1];
                    mma_f16(acc[0][nt], afr[0], b0, b1);
                    mma_f16(acc[1][nt], afr[1], b0, b1);
                }
            }
        }

        if (t + 1 < UT_TILES) CP_ASYNC_WAIT_ALL();
        __syncthreads();
    }

    // ---- Z partial reduce (reuse dead P buffer) + atomic flush ----
    float* zbuf = (float*)(sm + PT_OFF);    // 64*4 floats = 1KB < PT_BYTES
    zbuf[pr * 4 + (tid & 3)] = zpart;
    __syncthreads();
    if (tid < BM) {
        float s = zbuf[tid * 4] + zbuf[tid * 4 + 1] +
                  zbuf[tid * 4 + 2] + zbuf[tid * 4 + 3];
        atomicAdd(&g_Z[i0 + tid], s);
    }

    // ---- numerator atomic flush ----
#pragma unroll
    for (int mt = 0; mt < 2; mt++) {
        int rA = i0 + warp_m * 32 + mt * 16 + (lane >> 2);
#pragma unroll
        for (int nt = 0; nt < 8; nt++) {
            int c = warp_n * 64 + nt * 8 + 2 * (lane & 3);
            atomicAdd(&g_num[(size_t)rA * D_OUT + c],           acc[mt][nt][0]);
            atomicAdd(&g_num[(size_t)rA * D_OUT + c + 1],       acc[mt][nt][1]);
            atomicAdd(&g_num[(size_t)(rA + 8) * D_OUT + c],     acc[mt][nt][2]);
            atomicAdd(&g_num[(size_t)(rA + 8) * D_OUT + c + 1], acc[mt][nt][3]);
        }
    }
}

// ---------------------------------------------------------------------------
// Finalize: out = elu(num / Z)
// ---------------------------------------------------------------------------
__global__ __launch_bounds__(512) void finalize(float* __restrict__ out) {
    int idx = blockIdx.x * 512 + threadIdx.x;       // 524288 float4
    int row = idx >> 6;                             // 64 float4 per row
    float iz = 1.f / g_Z[row];
    float4 v = ((const float4*)g_num)[idx];
    float a = v.x * iz, b = v.y * iz, c = v.z * iz, d = v.w * iz;
    float4 o;
    o.x = (a > 0.f) ? a : (__expf(a) - 1.f);
    o.y = (b > 0.f) ? b : (__expf(b) - 1.f);
    o.z = (c > 0.f) ? c : (__expf(c) - 1.f);
    o.w = (d > 0.f) ? d : (__expf(d) - 1.f);
    ((float4*)out)[idx] = o;
}

// ---------------------------------------------------------------------------
extern "C" void kernel_launch(void* const* d_in, const int* in_sizes, int n_in,
                              void* d_out, int out_size) {
    const float* features = (const float*)d_in[0];
    const int*   adj      = (const int*)d_in[1];
    const float* W_phi    = (const float*)d_in[2];
    const float* w_mu     = (const float*)d_in[3];
    const float* w_xi     = (const float*)d_in[4];
    float* out = (float*)d_out;

    (void)in_sizes; (void)n_in; (void)out_size;

    zero_kernel<<<(N_NODES * D_OUT / 4) / 512, 512>>>();

    dim3 gA(N_NODES / 64, D_OUT / 64);
    gemm_xw<<<gA, 256>>>(features, W_phi);

    mu_xi_kernel<<<(N_NODES * 32) / 256, 256>>>(w_mu, w_xi);

    cudaFuncSetAttribute(attn_agg, cudaFuncAttributeMaxDynamicSharedMemorySize,
                         SM_BYTES);
    attn_agg<<<(N_NODES / BM) * 8, 256, SM_BYTES>>>(adj);

    finalize<<<(N_NODES * D_OUT / 4) / 512, 512>>>(out);
}